// round 12
// baseline (speedup 1.0000x reference)
#include <cuda_runtime.h>
#include <cuda_bf16.h>
#include <cstdint>
#include <cstddef>

// Problem constants
#define Bb 2
#define Ss 2048
#define Dd 1024
#define Hh 16
#define HDim 64
#define Mm 4096
#define NTOK (Bb*Ss)          // 4096
#define FOURD (4*Dd)          // 4096
#define EPS 1e-5f

// ---------------- scratch ----------------------------------------------------
__device__ float g_y[(size_t)NTOK * Dd];      // gated attention out
__device__ float g_t[(size_t)NTOK * Dd];      // GEMM2 out
__device__ __nv_bfloat16 g_xh[(size_t)NTOK * Dd],  g_xl[(size_t)NTOK * Dd];
__device__ __nv_bfloat16 g_w1h[(size_t)FOURD * Dd], g_w1l[(size_t)FOURD * Dd];
__device__ __nv_bfloat16 g_w2h[(size_t)Dd * Dd],   g_w2l[(size_t)Dd * Dd];
__device__ __nv_bfloat16 g_zh[(size_t)NTOK * Dd],  g_zl[(size_t)NTOK * Dd];
__device__ __nv_bfloat16 g_hh[(size_t)NTOK * FOURD], g_hl[(size_t)NTOK * FOURD];

// ---------------- common helpers ----------------------------------------------
__device__ __forceinline__ void mma_bf16(float* c, const uint32_t* a, const uint32_t* b) {
    asm volatile(
        "mma.sync.aligned.m16n8k16.row.col.f32.bf16.bf16.f32 "
        "{%0,%1,%2,%3}, {%4,%5,%6,%7}, {%8,%9}, {%0,%1,%2,%3};"
        : "+f"(c[0]), "+f"(c[1]), "+f"(c[2]), "+f"(c[3])
        : "r"(a[0]), "r"(a[1]), "r"(a[2]), "r"(a[3]), "r"(b[0]), "r"(b[1]));
}
__device__ __forceinline__ void ldm_x4(uint32_t* r, uint32_t addr) {
    asm volatile("ldmatrix.sync.aligned.m8n8.x4.shared.b16 {%0,%1,%2,%3}, [%4];"
        : "=r"(r[0]), "=r"(r[1]), "=r"(r[2]), "=r"(r[3]) : "r"(addr));
}
__device__ __forceinline__ void ldm_x4t(uint32_t* r, uint32_t addr) {
    asm volatile("ldmatrix.sync.aligned.m8n8.x4.trans.shared.b16 {%0,%1,%2,%3}, [%4];"
        : "=r"(r[0]), "=r"(r[1]), "=r"(r[2]), "=r"(r[3]) : "r"(addr));
}
__device__ __forceinline__ uint2 cvt_hi(float4 g, float4* rem) {
    __nv_bfloat16 h0 = __float2bfloat16(g.x), h1 = __float2bfloat16(g.y);
    __nv_bfloat16 h2 = __float2bfloat16(g.z), h3 = __float2bfloat16(g.w);
    rem->x = g.x - __bfloat162float(h0);
    rem->y = g.y - __bfloat162float(h1);
    rem->z = g.z - __bfloat162float(h2);
    rem->w = g.w - __bfloat162float(h3);
    __nv_bfloat162 p0(h0, h1), p1(h2, h3);
    return make_uint2(*(uint32_t*)&p0, *(uint32_t*)&p1);
}
__device__ __forceinline__ uint2 cvt_lo(float4 g) {
    __nv_bfloat16 l0 = __float2bfloat16(g.x), l1 = __float2bfloat16(g.y);
    __nv_bfloat16 l2 = __float2bfloat16(g.z), l3 = __float2bfloat16(g.w);
    __nv_bfloat162 p0(l0, l1), p1(l2, l3);
    return make_uint2(*(uint32_t*)&p0, *(uint32_t*)&p1);
}
__device__ __forceinline__ uint32_t pack_hi2(float a, float b, uint32_t* lo) {
    __nv_bfloat16 ha = __float2bfloat16(a), hb = __float2bfloat16(b);
    __nv_bfloat162 l(__float2bfloat16(a - __bfloat162float(ha)),
                     __float2bfloat16(b - __bfloat162float(hb)));
    *lo = *(uint32_t*)&l;
    __nv_bfloat162 h(ha, hb);
    return *(uint32_t*)&h;
}
__device__ __forceinline__ float silu_f(float v) {
    return v / (1.f + __expf(-v));
}
__device__ __forceinline__ uint32_t smem_u32(const void* p) {
    uint32_t a;
    asm("{ .reg .u64 t; cvta.to.shared.u64 t, %1; cvt.u32.u64 %0, t; }"
        : "=r"(a) : "l"(p));
    return a;
}
__device__ __forceinline__ void cp16(uint32_t dst, const void* src) {
    asm volatile("cp.async.cg.shared.global [%0], [%1], 16;" :: "r"(dst), "l"(src));
}
__device__ __forceinline__ void cp_commit() {
    asm volatile("cp.async.commit_group;" ::: "memory");
}
template<int N>
__device__ __forceinline__ void cp_wait() {
    asm volatile("cp.async.wait_group %0;" :: "n"(N) : "memory");
}

// ---------------- fp32 -> bf16 hi/lo converter (all 3 arrays, one launch) ------
__global__ __launch_bounds__(256)
void cvt3_kernel(const float* __restrict__ in0, __nv_bfloat16* __restrict__ h0,
                 __nv_bfloat16* __restrict__ l0, int n0,
                 const float* __restrict__ in1, __nv_bfloat16* __restrict__ h1,
                 __nv_bfloat16* __restrict__ l1, int n1,
                 const float* __restrict__ in2, __nv_bfloat16* __restrict__ h2,
                 __nv_bfloat16* __restrict__ l2, int n2) {
    const int total = n0 + n1 + n2;
    for (int i = blockIdx.x * 256 + threadIdx.x; i < total; i += gridDim.x * 256) {
        const float* in; __nv_bfloat16 *hi, *lo; int j;
        if (i < n0)            { in = in0; hi = h0; lo = l0; j = i; }
        else if (i < n0 + n1)  { in = in1; hi = h1; lo = l1; j = i - n0; }
        else                   { in = in2; hi = h2; lo = l2; j = i - n0 - n1; }
        float4 v = *(const float4*)&in[(size_t)j * 4];
        float4 rem;
        uint2 h = cvt_hi(v, &rem);
        *(uint2*)&hi[(size_t)j * 4] = h;
        *(uint2*)&lo[(size_t)j * 4] = cvt_lo(rem);
    }
}

// ============================================================================
// bf16 hi/lo HMMA GEMM (persistent CTAs, per-njp B-fragment loads)
// 256 thr, 128x128 tile, 2-stage cp.async, 2 CTAs/SM.
// ============================================================================
#define BM 128
#define BN 128
#define KC 32
#define PWW 20                         // SMEM row pitch in words (80 B)
#define TILEW (128 * PWW)              // words per tile (10240 B)
#define STGW  (4 * TILEW)              // words per stage 40960 B
#define GSMEM_BYTES (2 * STGW * 4)     // 81920
#define GPERSIST 296                   // 148 SMs x 2 CTAs

template<bool SILU, bool OBF16>
__global__ __launch_bounds__(256, 2)
void hmma_gemm_cp(const __nv_bfloat16* __restrict__ Ahg, const __nv_bfloat16* __restrict__ Alg,
                  const __nv_bfloat16* __restrict__ Bhg, const __nv_bfloat16* __restrict__ Blg,
                  const float* __restrict__ bias, float* __restrict__ C,
                  __nv_bfloat16* __restrict__ Ch, __nv_bfloat16* __restrict__ Cl,
                  int N, int K, int ntiles) {
    extern __shared__ __align__(16) uint32_t sw[];
    const uint32_t smb = smem_u32(sw);
    const int tid  = threadIdx.x;
    const int wid  = tid >> 5;
    const int lane = tid & 31;
    const int g = lane >> 2, t = lane & 3;
    const int wm = (wid >> 2) * 64;
    const int wn = (wid & 3) * 32;
    const int ntN = N / BN;

    const int li = lane >> 3, lr = lane & 7;
    const int a_row = (li & 1) * 8 + lr;
    const int a_wrd = (li >> 1) * 4;
    const int b_row = (li >> 1) * 8 + lr;
    const int b_wrd = (li & 1) * 4;

    const __nv_bfloat16* tp[4] = {Ahg, Alg, Bhg, Blg};
    const int nc = K / KC;

    for (int tile = blockIdx.x; tile < ntiles; tile += gridDim.x) {
        const int m0 = (tile / ntN) * BM;
        const int n0 = (tile % ntN) * BN;

        __syncthreads();   // SMEM from previous tile fully consumed

        auto issue_chunk = [&](int c) {
            const int k0 = c * KC;
            const uint32_t stg_b = smb + (c & 1) * (STGW * 4);
            #pragma unroll
            for (int it = 0; it < 8; it++) {
                int idx = it * 256 + tid;
                int tl = idx >> 9;
                int r = (idx >> 2) & 127;
                int q = idx & 3;
                int row = (tl < 2 ? m0 : n0) + r;
                const __nv_bfloat16* src = tp[tl] + (size_t)row * K + k0 + q * 8;
                cp16(stg_b + tl * (TILEW * 4) + r * 80 + q * 16, src);
            }
            cp_commit();
        };

        float acc[4][4][4];
        #pragma unroll
        for (int i = 0; i < 4; i++)
            #pragma unroll
            for (int j = 0; j < 4; j++)
                #pragma unroll
                for (int e = 0; e < 4; e++) acc[i][j][e] = 0.f;

        issue_chunk(0);

        for (int c = 0; c < nc; c++) {
            cp_wait<0>();
            __syncthreads();

            const uint32_t stg = smb + (c & 1) * (STGW * 4);
            const uint32_t AhB = stg;
            const uint32_t AlB = stg +     TILEW * 4;
            const uint32_t BhB = stg + 2 * TILEW * 4;
            const uint32_t BlB = stg + 3 * TILEW * 4;

            #pragma unroll
            for (int ks = 0; ks < 2; ks++) {
                uint32_t ah[4][4], al[4][4];
                #pragma unroll
                for (int mi = 0; mi < 4; mi++) {
                    const uint32_t ao = ((wm + mi * 16 + a_row) * PWW + ks * 8 + a_wrd) * 4;
                    ldm_x4(ah[mi], AhB + ao);
                    ldm_x4(al[mi], AlB + ao);
                }
                if (ks == 0 && c + 1 < nc) issue_chunk(c + 1);
                #pragma unroll
                for (int njp = 0; njp < 2; njp++) {
                    uint32_t bh4[4], bl4[4];
                    const uint32_t bo = ((wn + njp * 16 + b_row) * PWW + ks * 8 + b_wrd) * 4;
                    ldm_x4(bh4, BhB + bo);
                    ldm_x4(bl4, BlB + bo);
                    #pragma unroll
                    for (int mi = 0; mi < 4; mi++)
                        #pragma unroll
                        for (int h = 0; h < 2; h++) {
                            float* a = acc[mi][2 * njp + h];
                            mma_bf16(a, ah[mi], bh4 + 2 * h);
                            mma_bf16(a, ah[mi], bl4 + 2 * h);
                            mma_bf16(a, al[mi], bh4 + 2 * h);
                        }
                }
            }
        }

        // ---- epilogue ----
        #pragma unroll
        for (int mi = 0; mi < 4; mi++) {
            const int r0 = m0 + wm + mi * 16 + g;
            #pragma unroll
            for (int nj = 0; nj < 4; nj++) {
                const int cc = n0 + wn + nj * 8 + 2 * t;
                const float b0 = bias[cc], b1 = bias[cc + 1];
                float v0 = acc[mi][nj][0] + b0;
                float v1 = acc[mi][nj][1] + b1;
                float v2 = acc[mi][nj][2] + b0;
                float v3 = acc[mi][nj][3] + b1;
                if (SILU) {
                    v0 = silu_f(v0); v1 = silu_f(v1);
                    v2 = silu_f(v2); v3 = silu_f(v3);
                }
                if (OBF16) {
                    uint32_t lo0, lo1;
                    uint32_t hi0 = pack_hi2(v0, v1, &lo0);
                    uint32_t hi1 = pack_hi2(v2, v3, &lo1);
                    *(uint32_t*)&Ch[(size_t)r0 * N + cc]       = hi0;
                    *(uint32_t*)&Cl[(size_t)r0 * N + cc]       = lo0;
                    *(uint32_t*)&Ch[(size_t)(r0 + 8) * N + cc] = hi1;
                    *(uint32_t*)&Cl[(size_t)(r0 + 8) * N + cc] = lo1;
                } else {
                    *(float2*)&C[(size_t)r0 * N + cc]       = make_float2(v0, v1);
                    *(float2*)&C[(size_t)(r0 + 8) * N + cc] = make_float2(v2, v3);
                }
            }
        }
    }
}

// ============================================================================
// HMMA flash attention (R8/R10 version, proven)
// ============================================================================
#define AQT 128
#define AKT 64
#define APW 36
#define NQT (Ss / AQT)

#define QH_OFF 0
#define QL_OFF (128 * APW)
#define BUF_OFF (2 * 128 * APW)
#define TILE_KV (64 * APW)
#define BUF_W (4 * TILE_KV)
#define ASMEM_BYTES ((BUF_OFF + 2 * BUF_W) * 4)

__global__ __launch_bounds__(256, 2)
void attn_hmma(const float* __restrict__ pos_w, float* __restrict__ y,
               const __nv_bfloat16* __restrict__ hh, const __nv_bfloat16* __restrict__ hl) {
    extern __shared__ __align__(16) uint32_t aw[];
    const uint32_t smb = smem_u32(aw);

    const int head = blockIdx.y;
    const int b    = blockIdx.z;
    const int tid  = threadIdx.x;
    const int wid  = tid >> 5;
    const int lane = tid & 31;
    const int g = lane >> 2, t = lane & 3;
    const int li = lane >> 3, lr = lane & 7;
    const int a_row = (li & 1) * 8 + lr;
    const int a_wrd = (li >> 1) * 4;
    const int b_row = (li >> 1) * 8 + lr;
    const int b_wrd = (li & 1) * 4;

    const __nv_bfloat16* hh_b = hh + (size_t)b * Ss * FOURD + head * HDim;
    const __nv_bfloat16* hl_b = hl + (size_t)b * Ss * FOURD + head * HDim;

    auto issue_q = [&](int q_cta) {
        #pragma unroll
        for (int it = 0; it < 8; it++) {
            int idx = it * 256 + tid;
            int part = idx >> 10;
            int r = (idx >> 3) & 127;
            int q8 = idx & 7;
            const __nv_bfloat16* src =
                (part ? hl_b : hh_b) + (size_t)(q_cta + r) * FOURD + 1024 + q8 * 8;
            cp16(smb + ((part ? QL_OFF : QH_OFF) + r * APW + q8 * 4) * 4, src);
        }
    };
    auto issue_kv = [&](int jt, int buf) {
        const int k0 = jt * AKT;
        const uint32_t base = BUF_OFF + buf * BUF_W;
        #pragma unroll
        for (int it = 0; it < 8; it++) {
            int idx = it * 256 + tid;
            int part = idx >> 9;
            int r = (idx >> 3) & 63;
            int q8 = idx & 7;
            const __nv_bfloat16* bg = (part & 1) ? hl_b : hh_b;
            const int quarter = (part >> 1) ? 3072 : 2048;
            const __nv_bfloat16* src = bg + (size_t)(k0 + r) * FOURD + quarter + q8 * 8;
            cp16(smb + (base + part * TILE_KV + r * APW + q8 * 4) * 4, src);
        }
        cp_commit();
    };

    #pragma unroll 1
    for (int sel = 0; sel < 2; sel++) {
        const int qt = sel == 0 ? (int)blockIdx.x : (NQT - 1 - (int)blockIdx.x);
        const int q_cta = qt * AQT;
        const int jtmax = 2 * qt + 1;
        const int q_warp = q_cta + wid * 16;

        __syncthreads();
        issue_q(q_cta);
        issue_kv(0, 0);

        float O[8][4];
        #pragma unroll
        for (int nj = 0; nj < 8; nj++)
            #pragma unroll
            for (int e = 0; e < 4; e++) O[nj][e] = 0.f;

        for (int jt = 0; jt <= jtmax; jt++) {
            cp_wait<0>();
            __syncthreads();
            if (jt < jtmax) issue_kv(jt + 1, (jt + 1) & 1);

            const uint32_t bufb = smb + (BUF_OFF + (jt & 1) * BUF_W) * 4;
            const uint32_t khB = bufb;
            const uint32_t klB = bufb + TILE_KV * 4;
            const uint32_t vhB = bufb + 2 * TILE_KV * 4;
            const uint32_t vlB = bufb + 3 * TILE_KV * 4;

            if (jt * AKT <= q_warp + 15) {
                float S[8][4];
                #pragma unroll
                for (int nj = 0; nj < 8; nj++)
                    #pragma unroll
                    for (int e = 0; e < 4; e++) S[nj][e] = 0.f;

                #pragma unroll
                for (int ks = 0; ks < 4; ks++) {
                    uint32_t ah[4], al[4];
                    const uint32_t qoff = ((wid * 16 + a_row) * APW + ks * 8 + a_wrd) * 4;
                    ldm_x4(ah, smb + QH_OFF * 4 + qoff);
                    ldm_x4(al, smb + QL_OFF * 4 + qoff);
                    #pragma unroll
                    for (int nj2 = 0; nj2 < 4; nj2++) {
                        uint32_t bh4[4], bl4[4];
                        const uint32_t koff = ((nj2 * 16 + b_row) * APW + ks * 8 + b_wrd) * 4;
                        ldm_x4(bh4, khB + koff);
                        ldm_x4(bl4, klB + koff);
                        mma_bf16(S[2*nj2],   ah, bh4);
                        mma_bf16(S[2*nj2],   ah, bl4);
                        mma_bf16(S[2*nj2],   al, bh4);
                        mma_bf16(S[2*nj2+1], ah, bh4 + 2);
                        mma_bf16(S[2*nj2+1], ah, bl4 + 2);
                        mma_bf16(S[2*nj2+1], al, bh4 + 2);
                    }
                }

                const int qg0 = q_warp + g;
                #pragma unroll
                for (int ks2 = 0; ks2 < 4; ks2++) {
                    uint32_t ph[4], pl[4];
                    #pragma unroll
                    for (int half = 0; half < 2; half++) {
                        const float* sc = S[2*ks2 + half];
                        const int kc = jt * AKT + (2*ks2 + half) * 8 + 2*t;
                        float p00 = silu_f(sc[0] + pos_w[Mm - 1 + kc     - qg0]);
                        float p01 = silu_f(sc[1] + pos_w[Mm - 1 + kc + 1 - qg0]);
                        float p10 = silu_f(sc[2] + pos_w[Mm - 1 + kc     - (qg0+8)]);
                        float p11 = silu_f(sc[3] + pos_w[Mm - 1 + kc + 1 - (qg0+8)]);
                        if (kc     > qg0)   p00 = 0.f;
                        if (kc + 1 > qg0)   p01 = 0.f;
                        if (kc     > qg0+8) p10 = 0.f;
                        if (kc + 1 > qg0+8) p11 = 0.f;
                        ph[0 + half*2] = pack_hi2(p00, p01, &pl[0 + half*2]);
                        ph[1 + half*2] = pack_hi2(p10, p11, &pl[1 + half*2]);
                    }
                    #pragma unroll
                    for (int nj2 = 0; nj2 < 4; nj2++) {
                        uint32_t vh4[4], vl4[4];
                        const uint32_t voff =
                            ((ks2 * 16 + (li & 1) * 8 + lr) * APW + nj2 * 8 + (li >> 1) * 4) * 4;
                        ldm_x4t(vh4, vhB + voff);
                        ldm_x4t(vl4, vlB + voff);
                        mma_bf16(O[2*nj2],   ph, vh4);
                        mma_bf16(O[2*nj2],   ph, vl4);
                        mma_bf16(O[2*nj2],   pl, vh4);
                        mma_bf16(O[2*nj2+1], ph, vh4 + 2);
                        mma_bf16(O[2*nj2+1], ph, vl4 + 2);
                        mma_bf16(O[2*nj2+1], pl, vh4 + 2);
                    }
                }
            }
        }

        #pragma unroll
        for (int nj = 0; nj < 8; nj++) {
            const int d = nj * 8 + 2 * t;
            #pragma unroll
            for (int half = 0; half < 2; half++) {
                const int q = q_warp + g + half * 8;
                const uint32_t uhp = *(const uint32_t*)&hh_b[(size_t)q * FOURD + d];
                const uint32_t ulp = *(const uint32_t*)&hl_b[(size_t)q * FOURD + d];
                const __nv_bfloat162 uh2 = *(const __nv_bfloat162*)&uhp;
                const __nv_bfloat162 ul2 = *(const __nv_bfloat162*)&ulp;
                float2 r;
                r.x = O[nj][half*2 + 0] * (__bfloat162float(uh2.x) + __bfloat162float(ul2.x));
                r.y = O[nj][half*2 + 1] * (__bfloat162float(uh2.y) + __bfloat162float(ul2.y));
                *(float2*)&y[((size_t)b * Ss + q) * Dd + head * HDim + d] = r;
            }
        }
    }
}

// ---------------- LayerNorm: warp-per-row, shfl-only reductions ----------------
__device__ __forceinline__ float warp_allsum(float v) {
    #pragma unroll
    for (int o = 16; o > 0; o >>= 1) v += __shfl_xor_sync(0xffffffffu, v, o);
    return v;
}

template<bool BF16OUT>
__global__ __launch_bounds__(256)
void ln_kernel(const float* __restrict__ in, const float* __restrict__ res,
               const float* __restrict__ g, const float* __restrict__ beta,
               float* __restrict__ out,
               __nv_bfloat16* __restrict__ outh, __nv_bfloat16* __restrict__ outl) {
    const int lane = threadIdx.x & 31;
    const size_t row = (size_t)blockIdx.x * 8 + (threadIdx.x >> 5);

    float4 v[8];
    float s = 0.f;
    #pragma unroll
    for (int k = 0; k < 8; k++) {
        const int c = (k * 32 + lane) * 4;
        v[k] = *(const float4*)&in[row * Dd + c];
        if (res) {
            float4 r = *(const float4*)&res[row * Dd + c];
            v[k].x += r.x; v[k].y += r.y; v[k].z += r.z; v[k].w += r.w;
        }
        s += v[k].x + v[k].y + v[k].z + v[k].w;
    }
    const float mu = warp_allsum(s) * (1.f / Dd);

    float sq = 0.f;
    #pragma unroll
    for (int k = 0; k < 8; k++) {
        v[k].x -= mu; v[k].y -= mu; v[k].z -= mu; v[k].w -= mu;
        sq += v[k].x*v[k].x + v[k].y*v[k].y + v[k].z*v[k].z + v[k].w*v[k].w;
    }
    const float inv = rsqrtf(warp_allsum(sq) * (1.f / Dd) + EPS);

    #pragma unroll
    for (int k = 0; k < 8; k++) {
        const int c = (k * 32 + lane) * 4;
        float4 gv = *(const float4*)&g[c];
        float4 bv = *(const float4*)&beta[c];
        float4 r;
        r.x = v[k].x * inv * gv.x + bv.x;
        r.y = v[k].y * inv * gv.y + bv.y;
        r.z = v[k].z * inv * gv.z + bv.z;
        r.w = v[k].w * inv * gv.w + bv.w;
        if (BF16OUT) {
            float4 rem;
            uint2 h = cvt_hi(r, &rem);
            *(uint2*)&outh[row * Dd + c] = h;
            *(uint2*)&outl[row * Dd + c] = cvt_lo(rem);
        } else {
            *(float4*)&out[row * Dd + c] = r;
        }
    }
}

// ---------------- launch ------------------------------------------------------
extern "C" void kernel_launch(void* const* d_in, const int* in_sizes, int n_in,
                              void* d_out, int out_size) {
    const float* x     = (const float*)d_in[0];
    const float* w1    = (const float*)d_in[2];
    const float* b1    = (const float*)d_in[3];
    const float* w2    = (const float*)d_in[4];
    const float* b2    = (const float*)d_in[5];
    const float* g1    = (const float*)d_in[6];
    const float* beta1 = (const float*)d_in[7];
    const float* g2    = (const float*)d_in[8];
    const float* beta2 = (const float*)d_in[9];
    const float* pos_w = (const float*)d_in[10];
    float* out = (float*)d_out;

    float *ybuf, *tbuf;
    __nv_bfloat16 *xh, *xl, *w1h, *w1l, *w2h, *w2l, *zh, *zl, *hhp, *hlp;
    cudaGetSymbolAddress((void**)&ybuf, g_y);
    cudaGetSymbolAddress((void**)&tbuf, g_t);
    cudaGetSymbolAddress((void**)&xh,  g_xh);  cudaGetSymbolAddress((void**)&xl,  g_xl);
    cudaGetSymbolAddress((void**)&w1h, g_w1h); cudaGetSymbolAddress((void**)&w1l, g_w1l);
    cudaGetSymbolAddress((void**)&w2h, g_w2h); cudaGetSymbolAddress((void**)&w2l, g_w2l);
    cudaGetSymbolAddress((void**)&zh,  g_zh);  cudaGetSymbolAddress((void**)&zl,  g_zl);
    cudaGetSymbolAddress((void**)&hhp, g_hh);  cudaGetSymbolAddress((void**)&hlp, g_hl);

    cudaFuncSetAttribute((const void*)hmma_gemm_cp<true,true>,
                         cudaFuncAttributeMaxDynamicSharedMemorySize, GSMEM_BYTES);
    cudaFuncSetAttribute((const void*)hmma_gemm_cp<false,false>,
                         cudaFuncAttributeMaxDynamicSharedMemorySize, GSMEM_BYTES);
    cudaFuncSetAttribute((const void*)attn_hmma,
                         cudaFuncAttributeMaxDynamicSharedMemorySize, ASMEM_BYTES);

    // 0) pre-convert x, w1, w2 to bf16 hi/lo (single launch)
    cvt3_kernel<<<1184, 256>>>(x, xh, xl, NTOK * Dd / 4,
                               w1, w1h, w1l, FOURD * Dd / 4,
                               w2, w2h, w2l, Dd * Dd / 4);

    // 1) h = silu(x @ w1^T + b1) -> bf16 hi/lo  (persistent: 296 CTAs, 1024 tiles)
    hmma_gemm_cp<true,true><<<GPERSIST, 256, GSMEM_BYTES>>>(
        xh, xl, w1h, w1l, b1, nullptr, hhp, hlp, FOURD, Dd,
        (NTOK/BM) * (FOURD/BN));

    // 2) fused HMMA attention + u gate -> g_y
    attn_hmma<<<dim3(NQT/2, Hh, Bb), 256, ASMEM_BYTES>>>(pos_w, ybuf, hhp, hlp);

    // 3) LN1 -> z (bf16 hi/lo)  (warp-per-row: 8 rows/CTA)
    ln_kernel<true><<<NTOK/8, 256>>>(ybuf, nullptr, g1, beta1, nullptr, zh, zl);

    // 4) t = z @ w2^T + b2 (fp32 out; 256 tiles, one per CTA)
    hmma_gemm_cp<false,false><<<(NTOK/BM) * (Dd/BN), 256, GSMEM_BYTES>>>(
        zh, zl, w2h, w2l, b2, tbuf, nullptr, nullptr, Dd, Dd,
        (NTOK/BM) * (Dd/BN));

    // 5) out = LN(t + x)
    ln_kernel<false><<<NTOK/8, 256>>>(tbuf, x, g2, beta2, out, nullptr, nullptr);
}

// round 13
// speedup vs baseline: 1.0470x; 1.0470x over previous
#include <cuda_runtime.h>
#include <cuda_bf16.h>
#include <cstdint>
#include <cstddef>

// Problem constants
#define Bb 2
#define Ss 2048
#define Dd 1024
#define Hh 16
#define HDim 64
#define Mm 4096
#define NTOK (Bb*Ss)          // 4096
#define FOURD (4*Dd)          // 4096
#define EPS 1e-5f

// ---------------- scratch ----------------------------------------------------
__device__ float g_y[(size_t)NTOK * Dd];      // gated attention out
__device__ float g_t[(size_t)NTOK * Dd];      // GEMM2 out
__device__ __nv_bfloat16 g_xh[(size_t)NTOK * Dd],  g_xl[(size_t)NTOK * Dd];
__device__ __nv_bfloat16 g_w1h[(size_t)FOURD * Dd], g_w1l[(size_t)FOURD * Dd];
__device__ __nv_bfloat16 g_w2h[(size_t)Dd * Dd],   g_w2l[(size_t)Dd * Dd];
__device__ __nv_bfloat16 g_zh[(size_t)NTOK * Dd],  g_zl[(size_t)NTOK * Dd];
__device__ __nv_bfloat16 g_hh[(size_t)NTOK * FOURD], g_hl[(size_t)NTOK * FOURD];

// ---------------- common helpers ----------------------------------------------
__device__ __forceinline__ void mma_bf16(float* c, const uint32_t* a, const uint32_t* b) {
    asm volatile(
        "mma.sync.aligned.m16n8k16.row.col.f32.bf16.bf16.f32 "
        "{%0,%1,%2,%3}, {%4,%5,%6,%7}, {%8,%9}, {%0,%1,%2,%3};"
        : "+f"(c[0]), "+f"(c[1]), "+f"(c[2]), "+f"(c[3])
        : "r"(a[0]), "r"(a[1]), "r"(a[2]), "r"(a[3]), "r"(b[0]), "r"(b[1]));
}
__device__ __forceinline__ void ldm_x4(uint32_t* r, uint32_t addr) {
    asm volatile("ldmatrix.sync.aligned.m8n8.x4.shared.b16 {%0,%1,%2,%3}, [%4];"
        : "=r"(r[0]), "=r"(r[1]), "=r"(r[2]), "=r"(r[3]) : "r"(addr));
}
__device__ __forceinline__ void ldm_x4t(uint32_t* r, uint32_t addr) {
    asm volatile("ldmatrix.sync.aligned.m8n8.x4.trans.shared.b16 {%0,%1,%2,%3}, [%4];"
        : "=r"(r[0]), "=r"(r[1]), "=r"(r[2]), "=r"(r[3]) : "r"(addr));
}
__device__ __forceinline__ uint2 cvt_hi(float4 g, float4* rem) {
    __nv_bfloat16 h0 = __float2bfloat16(g.x), h1 = __float2bfloat16(g.y);
    __nv_bfloat16 h2 = __float2bfloat16(g.z), h3 = __float2bfloat16(g.w);
    rem->x = g.x - __bfloat162float(h0);
    rem->y = g.y - __bfloat162float(h1);
    rem->z = g.z - __bfloat162float(h2);
    rem->w = g.w - __bfloat162float(h3);
    __nv_bfloat162 p0(h0, h1), p1(h2, h3);
    return make_uint2(*(uint32_t*)&p0, *(uint32_t*)&p1);
}
__device__ __forceinline__ uint2 cvt_lo(float4 g) {
    __nv_bfloat16 l0 = __float2bfloat16(g.x), l1 = __float2bfloat16(g.y);
    __nv_bfloat16 l2 = __float2bfloat16(g.z), l3 = __float2bfloat16(g.w);
    __nv_bfloat162 p0(l0, l1), p1(l2, l3);
    return make_uint2(*(uint32_t*)&p0, *(uint32_t*)&p1);
}
__device__ __forceinline__ uint32_t pack_hi2(float a, float b, uint32_t* lo) {
    __nv_bfloat16 ha = __float2bfloat16(a), hb = __float2bfloat16(b);
    __nv_bfloat162 l(__float2bfloat16(a - __bfloat162float(ha)),
                     __float2bfloat16(b - __bfloat162float(hb)));
    *lo = *(uint32_t*)&l;
    __nv_bfloat162 h(ha, hb);
    return *(uint32_t*)&h;
}
__device__ __forceinline__ float silu_f(float v) {
    return v / (1.f + __expf(-v));
}
__device__ __forceinline__ uint32_t smem_u32(const void* p) {
    uint32_t a;
    asm("{ .reg .u64 t; cvta.to.shared.u64 t, %1; cvt.u32.u64 %0, t; }"
        : "=r"(a) : "l"(p));
    return a;
}
__device__ __forceinline__ void cp16(uint32_t dst, const void* src) {
    asm volatile("cp.async.cg.shared.global [%0], [%1], 16;" :: "r"(dst), "l"(src));
}
__device__ __forceinline__ void cp_commit() {
    asm volatile("cp.async.commit_group;" ::: "memory");
}
template<int N>
__device__ __forceinline__ void cp_wait() {
    asm volatile("cp.async.wait_group %0;" :: "n"(N) : "memory");
}

// ---------------- fp32 -> bf16 hi/lo converter (all 3 arrays, one launch) ------
__global__ __launch_bounds__(256)
void cvt3_kernel(const float* __restrict__ in0, __nv_bfloat16* __restrict__ h0,
                 __nv_bfloat16* __restrict__ l0, int n0,
                 const float* __restrict__ in1, __nv_bfloat16* __restrict__ h1,
                 __nv_bfloat16* __restrict__ l1, int n1,
                 const float* __restrict__ in2, __nv_bfloat16* __restrict__ h2,
                 __nv_bfloat16* __restrict__ l2, int n2) {
    const int total = n0 + n1 + n2;
    for (int i = blockIdx.x * 256 + threadIdx.x; i < total; i += gridDim.x * 256) {
        const float* in; __nv_bfloat16 *hi, *lo; int j;
        if (i < n0)            { in = in0; hi = h0; lo = l0; j = i; }
        else if (i < n0 + n1)  { in = in1; hi = h1; lo = l1; j = i - n0; }
        else                   { in = in2; hi = h2; lo = l2; j = i - n0 - n1; }
        float4 v = *(const float4*)&in[(size_t)j * 4];
        float4 rem;
        uint2 h = cvt_hi(v, &rem);
        *(uint2*)&hi[(size_t)j * 4] = h;
        *(uint2*)&lo[(size_t)j * 4] = cvt_lo(rem);
    }
}

// ============================================================================
// bf16 hi/lo HMMA GEMM (persistent CTAs; R11 proven inner loop)
// 256 thr, 128x128 tile, 2-stage cp.async, 2 CTAs/SM.
// ============================================================================
#define BM 128
#define BN 128
#define KC 32
#define PWW 20                         // SMEM row pitch in words (80 B)
#define TILEW (128 * PWW)              // words per tile (10240 B)
#define STGW  (4 * TILEW)              // words per stage 40960 B
#define GSMEM_BYTES (2 * STGW * 4)     // 81920
#define GPERSIST 296                   // 148 SMs x 2 CTAs

template<bool SILU, bool OBF16>
__global__ __launch_bounds__(256, 2)
void hmma_gemm_cp(const __nv_bfloat16* __restrict__ Ahg, const __nv_bfloat16* __restrict__ Alg,
                  const __nv_bfloat16* __restrict__ Bhg, const __nv_bfloat16* __restrict__ Blg,
                  const float* __restrict__ bias, float* __restrict__ C,
                  __nv_bfloat16* __restrict__ Ch, __nv_bfloat16* __restrict__ Cl,
                  int N, int K, int ntiles) {
    extern __shared__ __align__(16) uint32_t sw[];
    const uint32_t smb = smem_u32(sw);
    const int tid  = threadIdx.x;
    const int wid  = tid >> 5;
    const int lane = tid & 31;
    const int g = lane >> 2, t = lane & 3;
    const int wm = (wid >> 2) * 64;
    const int wn = (wid & 3) * 32;
    const int ntN = N / BN;

    const int li = lane >> 3, lr = lane & 7;
    const int a_row = (li & 1) * 8 + lr;
    const int a_wrd = (li >> 1) * 4;
    const int b_row = (li >> 1) * 8 + lr;
    const int b_wrd = (li & 1) * 4;

    const __nv_bfloat16* tp[4] = {Ahg, Alg, Bhg, Blg};
    const int nc = K / KC;

    for (int tile = blockIdx.x; tile < ntiles; tile += gridDim.x) {
        const int m0 = (tile / ntN) * BM;
        const int n0 = (tile % ntN) * BN;

        __syncthreads();   // SMEM from previous tile fully consumed

        auto issue_chunk = [&](int c) {
            const int k0 = c * KC;
            const uint32_t stg_b = smb + (c & 1) * (STGW * 4);
            #pragma unroll
            for (int it = 0; it < 8; it++) {
                int idx = it * 256 + tid;
                int tl = idx >> 9;
                int r = (idx >> 2) & 127;
                int q = idx & 3;
                int row = (tl < 2 ? m0 : n0) + r;
                const __nv_bfloat16* src = tp[tl] + (size_t)row * K + k0 + q * 8;
                cp16(stg_b + tl * (TILEW * 4) + r * 80 + q * 16, src);
            }
            cp_commit();
        };

        float acc[4][4][4];
        #pragma unroll
        for (int i = 0; i < 4; i++)
            #pragma unroll
            for (int j = 0; j < 4; j++)
                #pragma unroll
                for (int e = 0; e < 4; e++) acc[i][j][e] = 0.f;

        issue_chunk(0);

        for (int c = 0; c < nc; c++) {
            cp_wait<0>();
            __syncthreads();

            const uint32_t stg = smb + (c & 1) * (STGW * 4);
            const uint32_t AhB = stg;
            const uint32_t AlB = stg +     TILEW * 4;
            const uint32_t BhB = stg + 2 * TILEW * 4;
            const uint32_t BlB = stg + 3 * TILEW * 4;

            // ---- ks = 0: fragments first (A and both B halves), then cp.async ----
            uint32_t ah[4][4], al[4][4], bh[2][4], bl[2][4];
            #pragma unroll
            for (int mi = 0; mi < 4; mi++) {
                const uint32_t ao = ((wm + mi * 16 + a_row) * PWW + a_wrd) * 4;
                ldm_x4(ah[mi], AhB + ao);
                ldm_x4(al[mi], AlB + ao);
            }
            #pragma unroll
            for (int njp = 0; njp < 2; njp++) {
                const uint32_t bo = ((wn + njp * 16 + b_row) * PWW + b_wrd) * 4;
                ldm_x4(bh[njp], BhB + bo);
                ldm_x4(bl[njp], BlB + bo);
            }
            if (c + 1 < nc) issue_chunk(c + 1);
            #pragma unroll
            for (int mi = 0; mi < 4; mi++)
                #pragma unroll
                for (int nj = 0; nj < 4; nj++) {
                    const uint32_t* bhp = &bh[nj >> 1][(nj & 1) * 2];
                    const uint32_t* blp = &bl[nj >> 1][(nj & 1) * 2];
                    mma_bf16(acc[mi][nj], ah[mi], bhp);
                    mma_bf16(acc[mi][nj], ah[mi], blp);
                    mma_bf16(acc[mi][nj], al[mi], bhp);
                }

            // ---- ks = 1 ----
            #pragma unroll
            for (int mi = 0; mi < 4; mi++) {
                const uint32_t ao = ((wm + mi * 16 + a_row) * PWW + 8 + a_wrd) * 4;
                ldm_x4(ah[mi], AhB + ao);
                ldm_x4(al[mi], AlB + ao);
            }
            #pragma unroll
            for (int njp = 0; njp < 2; njp++) {
                const uint32_t bo = ((wn + njp * 16 + b_row) * PWW + 8 + b_wrd) * 4;
                ldm_x4(bh[njp], BhB + bo);
                ldm_x4(bl[njp], BlB + bo);
            }
            #pragma unroll
            for (int mi = 0; mi < 4; mi++)
                #pragma unroll
                for (int nj = 0; nj < 4; nj++) {
                    const uint32_t* bhp = &bh[nj >> 1][(nj & 1) * 2];
                    const uint32_t* blp = &bl[nj >> 1][(nj & 1) * 2];
                    mma_bf16(acc[mi][nj], ah[mi], bhp);
                    mma_bf16(acc[mi][nj], ah[mi], blp);
                    mma_bf16(acc[mi][nj], al[mi], bhp);
                }
        }

        // ---- epilogue ----
        #pragma unroll
        for (int mi = 0; mi < 4; mi++) {
            const int r0 = m0 + wm + mi * 16 + g;
            #pragma unroll
            for (int nj = 0; nj < 4; nj++) {
                const int cc = n0 + wn + nj * 8 + 2 * t;
                const float b0 = bias[cc], b1 = bias[cc + 1];
                float v0 = acc[mi][nj][0] + b0;
                float v1 = acc[mi][nj][1] + b1;
                float v2 = acc[mi][nj][2] + b0;
                float v3 = acc[mi][nj][3] + b1;
                if (SILU) {
                    v0 = silu_f(v0); v1 = silu_f(v1);
                    v2 = silu_f(v2); v3 = silu_f(v3);
                }
                if (OBF16) {
                    uint32_t lo0, lo1;
                    uint32_t hi0 = pack_hi2(v0, v1, &lo0);
                    uint32_t hi1 = pack_hi2(v2, v3, &lo1);
                    *(uint32_t*)&Ch[(size_t)r0 * N + cc]       = hi0;
                    *(uint32_t*)&Cl[(size_t)r0 * N + cc]       = lo0;
                    *(uint32_t*)&Ch[(size_t)(r0 + 8) * N + cc] = hi1;
                    *(uint32_t*)&Cl[(size_t)(r0 + 8) * N + cc] = lo1;
                } else {
                    *(float2*)&C[(size_t)r0 * N + cc]       = make_float2(v0, v1);
                    *(float2*)&C[(size_t)(r0 + 8) * N + cc] = make_float2(v2, v3);
                }
            }
        }
    }
}

// ============================================================================
// HMMA flash attention (R8/R10/R11 version, proven)
// ============================================================================
#define AQT 128
#define AKT 64
#define APW 36
#define NQT (Ss / AQT)

#define QH_OFF 0
#define QL_OFF (128 * APW)
#define BUF_OFF (2 * 128 * APW)
#define TILE_KV (64 * APW)
#define BUF_W (4 * TILE_KV)
#define ASMEM_BYTES ((BUF_OFF + 2 * BUF_W) * 4)

__global__ __launch_bounds__(256, 2)
void attn_hmma(const float* __restrict__ pos_w, float* __restrict__ y,
               const __nv_bfloat16* __restrict__ hh, const __nv_bfloat16* __restrict__ hl) {
    extern __shared__ __align__(16) uint32_t aw[];
    const uint32_t smb = smem_u32(aw);

    const int head = blockIdx.y;
    const int b    = blockIdx.z;
    const int tid  = threadIdx.x;
    const int wid  = tid >> 5;
    const int lane = tid & 31;
    const int g = lane >> 2, t = lane & 3;
    const int li = lane >> 3, lr = lane & 7;
    const int a_row = (li & 1) * 8 + lr;
    const int a_wrd = (li >> 1) * 4;
    const int b_row = (li >> 1) * 8 + lr;
    const int b_wrd = (li & 1) * 4;

    const __nv_bfloat16* hh_b = hh + (size_t)b * Ss * FOURD + head * HDim;
    const __nv_bfloat16* hl_b = hl + (size_t)b * Ss * FOURD + head * HDim;

    auto issue_q = [&](int q_cta) {
        #pragma unroll
        for (int it = 0; it < 8; it++) {
            int idx = it * 256 + tid;
            int part = idx >> 10;
            int r = (idx >> 3) & 127;
            int q8 = idx & 7;
            const __nv_bfloat16* src =
                (part ? hl_b : hh_b) + (size_t)(q_cta + r) * FOURD + 1024 + q8 * 8;
            cp16(smb + ((part ? QL_OFF : QH_OFF) + r * APW + q8 * 4) * 4, src);
        }
    };
    auto issue_kv = [&](int jt, int buf) {
        const int k0 = jt * AKT;
        const uint32_t base = BUF_OFF + buf * BUF_W;
        #pragma unroll
        for (int it = 0; it < 8; it++) {
            int idx = it * 256 + tid;
            int part = idx >> 9;
            int r = (idx >> 3) & 63;
            int q8 = idx & 7;
            const __nv_bfloat16* bg = (part & 1) ? hl_b : hh_b;
            const int quarter = (part >> 1) ? 3072 : 2048;
            const __nv_bfloat16* src = bg + (size_t)(k0 + r) * FOURD + quarter + q8 * 8;
            cp16(smb + (base + part * TILE_KV + r * APW + q8 * 4) * 4, src);
        }
        cp_commit();
    };

    #pragma unroll 1
    for (int sel = 0; sel < 2; sel++) {
        const int qt = sel == 0 ? (int)blockIdx.x : (NQT - 1 - (int)blockIdx.x);
        const int q_cta = qt * AQT;
        const int jtmax = 2 * qt + 1;
        const int q_warp = q_cta + wid * 16;

        __syncthreads();
        issue_q(q_cta);
        issue_kv(0, 0);

        float O[8][4];
        #pragma unroll
        for (int nj = 0; nj < 8; nj++)
            #pragma unroll
            for (int e = 0; e < 4; e++) O[nj][e] = 0.f;

        for (int jt = 0; jt <= jtmax; jt++) {
            cp_wait<0>();
            __syncthreads();
            if (jt < jtmax) issue_kv(jt + 1, (jt + 1) & 1);

            const uint32_t bufb = smb + (BUF_OFF + (jt & 1) * BUF_W) * 4;
            const uint32_t khB = bufb;
            const uint32_t klB = bufb + TILE_KV * 4;
            const uint32_t vhB = bufb + 2 * TILE_KV * 4;
            const uint32_t vlB = bufb + 3 * TILE_KV * 4;

            if (jt * AKT <= q_warp + 15) {
                float S[8][4];
                #pragma unroll
                for (int nj = 0; nj < 8; nj++)
                    #pragma unroll
                    for (int e = 0; e < 4; e++) S[nj][e] = 0.f;

                #pragma unroll
                for (int ks = 0; ks < 4; ks++) {
                    uint32_t ah[4], al[4];
                    const uint32_t qoff = ((wid * 16 + a_row) * APW + ks * 8 + a_wrd) * 4;
                    ldm_x4(ah, smb + QH_OFF * 4 + qoff);
                    ldm_x4(al, smb + QL_OFF * 4 + qoff);
                    #pragma unroll
                    for (int nj2 = 0; nj2 < 4; nj2++) {
                        uint32_t bh4[4], bl4[4];
                        const uint32_t koff = ((nj2 * 16 + b_row) * APW + ks * 8 + b_wrd) * 4;
                        ldm_x4(bh4, khB + koff);
                        ldm_x4(bl4, klB + koff);
                        mma_bf16(S[2*nj2],   ah, bh4);
                        mma_bf16(S[2*nj2],   ah, bl4);
                        mma_bf16(S[2*nj2],   al, bh4);
                        mma_bf16(S[2*nj2+1], ah, bh4 + 2);
                        mma_bf16(S[2*nj2+1], ah, bl4 + 2);
                        mma_bf16(S[2*nj2+1], al, bh4 + 2);
                    }
                }

                const int qg0 = q_warp + g;
                #pragma unroll
                for (int ks2 = 0; ks2 < 4; ks2++) {
                    uint32_t ph[4], pl[4];
                    #pragma unroll
                    for (int half = 0; half < 2; half++) {
                        const float* sc = S[2*ks2 + half];
                        const int kc = jt * AKT + (2*ks2 + half) * 8 + 2*t;
                        float p00 = silu_f(sc[0] + pos_w[Mm - 1 + kc     - qg0]);
                        float p01 = silu_f(sc[1] + pos_w[Mm - 1 + kc + 1 - qg0]);
                        float p10 = silu_f(sc[2] + pos_w[Mm - 1 + kc     - (qg0+8)]);
                        float p11 = silu_f(sc[3] + pos_w[Mm - 1 + kc + 1 - (qg0+8)]);
                        if (kc     > qg0)   p00 = 0.f;
                        if (kc + 1 > qg0)   p01 = 0.f;
                        if (kc     > qg0+8) p10 = 0.f;
                        if (kc + 1 > qg0+8) p11 = 0.f;
                        ph[0 + half*2] = pack_hi2(p00, p01, &pl[0 + half*2]);
                        ph[1 + half*2] = pack_hi2(p10, p11, &pl[1 + half*2]);
                    }
                    #pragma unroll
                    for (int nj2 = 0; nj2 < 4; nj2++) {
                        uint32_t vh4[4], vl4[4];
                        const uint32_t voff =
                            ((ks2 * 16 + (li & 1) * 8 + lr) * APW + nj2 * 8 + (li >> 1) * 4) * 4;
                        ldm_x4t(vh4, vhB + voff);
                        ldm_x4t(vl4, vlB + voff);
                        mma_bf16(O[2*nj2],   ph, vh4);
                        mma_bf16(O[2*nj2],   ph, vl4);
                        mma_bf16(O[2*nj2],   pl, vh4);
                        mma_bf16(O[2*nj2+1], ph, vh4 + 2);
                        mma_bf16(O[2*nj2+1], ph, vl4 + 2);
                        mma_bf16(O[2*nj2+1], pl, vh4 + 2);
                    }
                }
            }
        }

        #pragma unroll
        for (int nj = 0; nj < 8; nj++) {
            const int d = nj * 8 + 2 * t;
            #pragma unroll
            for (int half = 0; half < 2; half++) {
                const int q = q_warp + g + half * 8;
                const uint32_t uhp = *(const uint32_t*)&hh_b[(size_t)q * FOURD + d];
                const uint32_t ulp = *(const uint32_t*)&hl_b[(size_t)q * FOURD + d];
                const __nv_bfloat162 uh2 = *(const __nv_bfloat162*)&uhp;
                const __nv_bfloat162 ul2 = *(const __nv_bfloat162*)&ulp;
                float2 r;
                r.x = O[nj][half*2 + 0] * (__bfloat162float(uh2.x) + __bfloat162float(ul2.x));
                r.y = O[nj][half*2 + 1] * (__bfloat162float(uh2.y) + __bfloat162float(ul2.y));
                *(float2*)&y[((size_t)b * Ss + q) * Dd + head * HDim + d] = r;
            }
        }
    }
}

// ---------------- LayerNorm: warp-per-row, shfl-only (R12, measured faster) ----
__device__ __forceinline__ float warp_allsum(float v) {
    #pragma unroll
    for (int o = 16; o > 0; o >>= 1) v += __shfl_xor_sync(0xffffffffu, v, o);
    return v;
}

template<bool BF16OUT>
__global__ __launch_bounds__(256)
void ln_kernel(const float* __restrict__ in, const float* __restrict__ res,
               const float* __restrict__ g, const float* __restrict__ beta,
               float* __restrict__ out,
               __nv_bfloat16* __restrict__ outh, __nv_bfloat16* __restrict__ outl) {
    const int lane = threadIdx.x & 31;
    const size_t row = (size_t)blockIdx.x * 8 + (threadIdx.x >> 5);

    float4 v[8];
    float s = 0.f;
    #pragma unroll
    for (int k = 0; k < 8; k++) {
        const int c = (k * 32 + lane) * 4;
        v[k] = *(const float4*)&in[row * Dd + c];
        if (res) {
            float4 r = *(const float4*)&res[row * Dd + c];
            v[k].x += r.x; v[k].y += r.y; v[k].z += r.z; v[k].w += r.w;
        }
        s += v[k].x + v[k].y + v[k].z + v[k].w;
    }
    const float mu = warp_allsum(s) * (1.f / Dd);

    float sq = 0.f;
    #pragma unroll
    for (int k = 0; k < 8; k++) {
        v[k].x -= mu; v[k].y -= mu; v[k].z -= mu; v[k].w -= mu;
        sq += v[k].x*v[k].x + v[k].y*v[k].y + v[k].z*v[k].z + v[k].w*v[k].w;
    }
    const float inv = rsqrtf(warp_allsum(sq) * (1.f / Dd) + EPS);

    #pragma unroll
    for (int k = 0; k < 8; k++) {
        const int c = (k * 32 + lane) * 4;
        float4 gv = *(const float4*)&g[c];
        float4 bv = *(const float4*)&beta[c];
        float4 r;
        r.x = v[k].x * inv * gv.x + bv.x;
        r.y = v[k].y * inv * gv.y + bv.y;
        r.z = v[k].z * inv * gv.z + bv.z;
        r.w = v[k].w * inv * gv.w + bv.w;
        if (BF16OUT) {
            float4 rem;
            uint2 h = cvt_hi(r, &rem);
            *(uint2*)&outh[row * Dd + c] = h;
            *(uint2*)&outl[row * Dd + c] = cvt_lo(rem);
        } else {
            *(float4*)&out[row * Dd + c] = r;
        }
    }
}

// ---------------- launch ------------------------------------------------------
extern "C" void kernel_launch(void* const* d_in, const int* in_sizes, int n_in,
                              void* d_out, int out_size) {
    const float* x     = (const float*)d_in[0];
    const float* w1    = (const float*)d_in[2];
    const float* b1    = (const float*)d_in[3];
    const float* w2    = (const float*)d_in[4];
    const float* b2    = (const float*)d_in[5];
    const float* g1    = (const float*)d_in[6];
    const float* beta1 = (const float*)d_in[7];
    const float* g2    = (const float*)d_in[8];
    const float* beta2 = (const float*)d_in[9];
    const float* pos_w = (const float*)d_in[10];
    float* out = (float*)d_out;

    float *ybuf, *tbuf;
    __nv_bfloat16 *xh, *xl, *w1h, *w1l, *w2h, *w2l, *zh, *zl, *hhp, *hlp;
    cudaGetSymbolAddress((void**)&ybuf, g_y);
    cudaGetSymbolAddress((void**)&tbuf, g_t);
    cudaGetSymbolAddress((void**)&xh,  g_xh);  cudaGetSymbolAddress((void**)&xl,  g_xl);
    cudaGetSymbolAddress((void**)&w1h, g_w1h); cudaGetSymbolAddress((void**)&w1l, g_w1l);
    cudaGetSymbolAddress((void**)&w2h, g_w2h); cudaGetSymbolAddress((void**)&w2l, g_w2l);
    cudaGetSymbolAddress((void**)&zh,  g_zh);  cudaGetSymbolAddress((void**)&zl,  g_zl);
    cudaGetSymbolAddress((void**)&hhp, g_hh);  cudaGetSymbolAddress((void**)&hlp, g_hl);

    cudaFuncSetAttribute((const void*)hmma_gemm_cp<true,true>,
                         cudaFuncAttributeMaxDynamicSharedMemorySize, GSMEM_BYTES);
    cudaFuncSetAttribute((const void*)hmma_gemm_cp<false,false>,
                         cudaFuncAttributeMaxDynamicSharedMemorySize, GSMEM_BYTES);
    cudaFuncSetAttribute((const void*)attn_hmma,
                         cudaFuncAttributeMaxDynamicSharedMemorySize, ASMEM_BYTES);

    // 0) pre-convert x, w1, w2 to bf16 hi/lo (single launch)
    cvt3_kernel<<<1184, 256>>>(x, xh, xl, NTOK * Dd / 4,
                               w1, w1h, w1l, FOURD * Dd / 4,
                               w2, w2h, w2l, Dd * Dd / 4);

    // 1) h = silu(x @ w1^T + b1) -> bf16 hi/lo  (persistent: 296 CTAs, 1024 tiles)
    hmma_gemm_cp<true,true><<<GPERSIST, 256, GSMEM_BYTES>>>(
        xh, xl, w1h, w1l, b1, nullptr, hhp, hlp, FOURD, Dd,
        (NTOK/BM) * (FOURD/BN));

    // 2) fused HMMA attention + u gate -> g_y
    attn_hmma<<<dim3(NQT/2, Hh, Bb), 256, ASMEM_BYTES>>>(pos_w, ybuf, hhp, hlp);

    // 3) LN1 -> z (bf16 hi/lo)  (warp-per-row)
    ln_kernel<true><<<NTOK/8, 256>>>(ybuf, nullptr, g1, beta1, nullptr, zh, zl);

    // 4) t = z @ w2^T + b2 (fp32 out; 256 tiles, one per CTA)
    hmma_gemm_cp<false,false><<<(NTOK/BM) * (Dd/BN), 256, GSMEM_BYTES>>>(
        zh, zl, w2h, w2l, b2, tbuf, nullptr, nullptr, Dd, Dd,
        (NTOK/BM) * (Dd/BN));

    // 5) out = LN(t + x)
    ln_kernel<false><<<NTOK/8, 256>>>(tbuf, x, g2, beta2, out, nullptr, nullptr);
}

// round 14
// speedup vs baseline: 1.0585x; 1.0110x over previous
#include <cuda_runtime.h>
#include <cuda_bf16.h>
#include <cstdint>
#include <cstddef>

// Problem constants
#define Bb 2
#define Ss 2048
#define Dd 1024
#define Hh 16
#define HDim 64
#define Mm 4096
#define NTOK (Bb*Ss)          // 4096
#define FOURD (4*Dd)          // 4096
#define EPS 1e-5f

// ---------------- scratch ----------------------------------------------------
__device__ float g_y[(size_t)NTOK * Dd];      // gated attention out
__device__ float g_t[(size_t)NTOK * Dd];      // GEMM2 out
__device__ __nv_bfloat16 g_xh[(size_t)NTOK * Dd],  g_xl[(size_t)NTOK * Dd];
__device__ __nv_bfloat16 g_w1h[(size_t)FOURD * Dd], g_w1l[(size_t)FOURD * Dd];
__device__ __nv_bfloat16 g_w2h[(size_t)Dd * Dd],   g_w2l[(size_t)Dd * Dd];
__device__ __nv_bfloat16 g_zh[(size_t)NTOK * Dd],  g_zl[(size_t)NTOK * Dd];
__device__ __nv_bfloat16 g_hh[(size_t)NTOK * FOURD], g_hl[(size_t)NTOK * FOURD];

// ---------------- common helpers ----------------------------------------------
__device__ __forceinline__ void mma_bf16(float* c, const uint32_t* a, const uint32_t* b) {
    asm volatile(
        "mma.sync.aligned.m16n8k16.row.col.f32.bf16.bf16.f32 "
        "{%0,%1,%2,%3}, {%4,%5,%6,%7}, {%8,%9}, {%0,%1,%2,%3};"
        : "+f"(c[0]), "+f"(c[1]), "+f"(c[2]), "+f"(c[3])
        : "r"(a[0]), "r"(a[1]), "r"(a[2]), "r"(a[3]), "r"(b[0]), "r"(b[1]));
}
__device__ __forceinline__ void ldm_x4(uint32_t* r, uint32_t addr) {
    asm volatile("ldmatrix.sync.aligned.m8n8.x4.shared.b16 {%0,%1,%2,%3}, [%4];"
        : "=r"(r[0]), "=r"(r[1]), "=r"(r[2]), "=r"(r[3]) : "r"(addr));
}
__device__ __forceinline__ void ldm_x4t(uint32_t* r, uint32_t addr) {
    asm volatile("ldmatrix.sync.aligned.m8n8.x4.trans.shared.b16 {%0,%1,%2,%3}, [%4];"
        : "=r"(r[0]), "=r"(r[1]), "=r"(r[2]), "=r"(r[3]) : "r"(addr));
}
__device__ __forceinline__ uint2 cvt_hi(float4 g, float4* rem) {
    __nv_bfloat16 h0 = __float2bfloat16(g.x), h1 = __float2bfloat16(g.y);
    __nv_bfloat16 h2 = __float2bfloat16(g.z), h3 = __float2bfloat16(g.w);
    rem->x = g.x - __bfloat162float(h0);
    rem->y = g.y - __bfloat162float(h1);
    rem->z = g.z - __bfloat162float(h2);
    rem->w = g.w - __bfloat162float(h3);
    __nv_bfloat162 p0(h0, h1), p1(h2, h3);
    return make_uint2(*(uint32_t*)&p0, *(uint32_t*)&p1);
}
__device__ __forceinline__ uint2 cvt_lo(float4 g) {
    __nv_bfloat16 l0 = __float2bfloat16(g.x), l1 = __float2bfloat16(g.y);
    __nv_bfloat16 l2 = __float2bfloat16(g.z), l3 = __float2bfloat16(g.w);
    __nv_bfloat162 p0(l0, l1), p1(l2, l3);
    return make_uint2(*(uint32_t*)&p0, *(uint32_t*)&p1);
}
__device__ __forceinline__ uint32_t pack_hi2(float a, float b, uint32_t* lo) {
    __nv_bfloat16 ha = __float2bfloat16(a), hb = __float2bfloat16(b);
    __nv_bfloat162 l(__float2bfloat16(a - __bfloat162float(ha)),
                     __float2bfloat16(b - __bfloat162float(hb)));
    *lo = *(uint32_t*)&l;
    __nv_bfloat162 h(ha, hb);
    return *(uint32_t*)&h;
}
__device__ __forceinline__ float silu_f(float v) {
    return v / (1.f + __expf(-v));
}
__device__ __forceinline__ uint32_t smem_u32(const void* p) {
    uint32_t a;
    asm("{ .reg .u64 t; cvta.to.shared.u64 t, %1; cvt.u32.u64 %0, t; }"
        : "=r"(a) : "l"(p));
    return a;
}
__device__ __forceinline__ void cp16(uint32_t dst, const void* src) {
    asm volatile("cp.async.cg.shared.global [%0], [%1], 16;" :: "r"(dst), "l"(src));
}
__device__ __forceinline__ void cp_commit() {
    asm volatile("cp.async.commit_group;" ::: "memory");
}
template<int N>
__device__ __forceinline__ void cp_wait() {
    asm volatile("cp.async.wait_group %0;" :: "n"(N) : "memory");
}

// ---------------- fp32 -> bf16 hi/lo converter (all 3 arrays, one launch) ------
__global__ __launch_bounds__(256)
void cvt3_kernel(const float* __restrict__ in0, __nv_bfloat16* __restrict__ h0,
                 __nv_bfloat16* __restrict__ l0, int n0,
                 const float* __restrict__ in1, __nv_bfloat16* __restrict__ h1,
                 __nv_bfloat16* __restrict__ l1, int n1,
                 const float* __restrict__ in2, __nv_bfloat16* __restrict__ h2,
                 __nv_bfloat16* __restrict__ l2, int n2) {
    const int total = n0 + n1 + n2;
    for (int i = blockIdx.x * 256 + threadIdx.x; i < total; i += gridDim.x * 256) {
        const float* in; __nv_bfloat16 *hi, *lo; int j;
        if (i < n0)            { in = in0; hi = h0; lo = l0; j = i; }
        else if (i < n0 + n1)  { in = in1; hi = h1; lo = l1; j = i - n0; }
        else                   { in = in2; hi = h2; lo = l2; j = i - n0 - n1; }
        float4 v = *(const float4*)&in[(size_t)j * 4];
        float4 rem;
        uint2 h = cvt_hi(v, &rem);
        *(uint2*)&hi[(size_t)j * 4] = h;
        *(uint2*)&lo[(size_t)j * 4] = cvt_lo(rem);
    }
}

// ============================================================================
// bf16 hi/lo HMMA GEMM (persistent CTAs; R11/R13 proven inner loop)
// ============================================================================
#define BM 128
#define BN 128
#define KC 32
#define PWW 20
#define TILEW (128 * PWW)
#define STGW  (4 * TILEW)
#define GSMEM_BYTES (2 * STGW * 4)
#define GPERSIST 296

template<bool SILU, bool OBF16>
__global__ __launch_bounds__(256, 2)
void hmma_gemm_cp(const __nv_bfloat16* __restrict__ Ahg, const __nv_bfloat16* __restrict__ Alg,
                  const __nv_bfloat16* __restrict__ Bhg, const __nv_bfloat16* __restrict__ Blg,
                  const float* __restrict__ bias, float* __restrict__ C,
                  __nv_bfloat16* __restrict__ Ch, __nv_bfloat16* __restrict__ Cl,
                  int N, int K, int ntiles) {
    extern __shared__ __align__(16) uint32_t sw[];
    const uint32_t smb = smem_u32(sw);
    const int tid  = threadIdx.x;
    const int wid  = tid >> 5;
    const int lane = tid & 31;
    const int g = lane >> 2, t = lane & 3;
    const int wm = (wid >> 2) * 64;
    const int wn = (wid & 3) * 32;
    const int ntN = N / BN;

    const int li = lane >> 3, lr = lane & 7;
    const int a_row = (li & 1) * 8 + lr;
    const int a_wrd = (li >> 1) * 4;
    const int b_row = (li >> 1) * 8 + lr;
    const int b_wrd = (li & 1) * 4;

    const __nv_bfloat16* tp[4] = {Ahg, Alg, Bhg, Blg};
    const int nc = K / KC;

    for (int tile = blockIdx.x; tile < ntiles; tile += gridDim.x) {
        const int m0 = (tile / ntN) * BM;
        const int n0 = (tile % ntN) * BN;

        __syncthreads();

        auto issue_chunk = [&](int c) {
            const int k0 = c * KC;
            const uint32_t stg_b = smb + (c & 1) * (STGW * 4);
            #pragma unroll
            for (int it = 0; it < 8; it++) {
                int idx = it * 256 + tid;
                int tl = idx >> 9;
                int r = (idx >> 2) & 127;
                int q = idx & 3;
                int row = (tl < 2 ? m0 : n0) + r;
                const __nv_bfloat16* src = tp[tl] + (size_t)row * K + k0 + q * 8;
                cp16(stg_b + tl * (TILEW * 4) + r * 80 + q * 16, src);
            }
            cp_commit();
        };

        float acc[4][4][4];
        #pragma unroll
        for (int i = 0; i < 4; i++)
            #pragma unroll
            for (int j = 0; j < 4; j++)
                #pragma unroll
                for (int e = 0; e < 4; e++) acc[i][j][e] = 0.f;

        issue_chunk(0);

        for (int c = 0; c < nc; c++) {
            cp_wait<0>();
            __syncthreads();

            const uint32_t stg = smb + (c & 1) * (STGW * 4);
            const uint32_t AhB = stg;
            const uint32_t AlB = stg +     TILEW * 4;
            const uint32_t BhB = stg + 2 * TILEW * 4;
            const uint32_t BlB = stg + 3 * TILEW * 4;

            uint32_t ah[4][4], al[4][4], bh[2][4], bl[2][4];
            #pragma unroll
            for (int mi = 0; mi < 4; mi++) {
                const uint32_t ao = ((wm + mi * 16 + a_row) * PWW + a_wrd) * 4;
                ldm_x4(ah[mi], AhB + ao);
                ldm_x4(al[mi], AlB + ao);
            }
            #pragma unroll
            for (int njp = 0; njp < 2; njp++) {
                const uint32_t bo = ((wn + njp * 16 + b_row) * PWW + b_wrd) * 4;
                ldm_x4(bh[njp], BhB + bo);
                ldm_x4(bl[njp], BlB + bo);
            }
            if (c + 1 < nc) issue_chunk(c + 1);
            #pragma unroll
            for (int mi = 0; mi < 4; mi++)
                #pragma unroll
                for (int nj = 0; nj < 4; nj++) {
                    const uint32_t* bhp = &bh[nj >> 1][(nj & 1) * 2];
                    const uint32_t* blp = &bl[nj >> 1][(nj & 1) * 2];
                    mma_bf16(acc[mi][nj], ah[mi], bhp);
                    mma_bf16(acc[mi][nj], ah[mi], blp);
                    mma_bf16(acc[mi][nj], al[mi], bhp);
                }

            #pragma unroll
            for (int mi = 0; mi < 4; mi++) {
                const uint32_t ao = ((wm + mi * 16 + a_row) * PWW + 8 + a_wrd) * 4;
                ldm_x4(ah[mi], AhB + ao);
                ldm_x4(al[mi], AlB + ao);
            }
            #pragma unroll
            for (int njp = 0; njp < 2; njp++) {
                const uint32_t bo = ((wn + njp * 16 + b_row) * PWW + 8 + b_wrd) * 4;
                ldm_x4(bh[njp], BhB + bo);
                ldm_x4(bl[njp], BlB + bo);
            }
            #pragma unroll
            for (int mi = 0; mi < 4; mi++)
                #pragma unroll
                for (int nj = 0; nj < 4; nj++) {
                    const uint32_t* bhp = &bh[nj >> 1][(nj & 1) * 2];
                    const uint32_t* blp = &bl[nj >> 1][(nj & 1) * 2];
                    mma_bf16(acc[mi][nj], ah[mi], bhp);
                    mma_bf16(acc[mi][nj], ah[mi], blp);
                    mma_bf16(acc[mi][nj], al[mi], bhp);
                }
        }

        #pragma unroll
        for (int mi = 0; mi < 4; mi++) {
            const int r0 = m0 + wm + mi * 16 + g;
            #pragma unroll
            for (int nj = 0; nj < 4; nj++) {
                const int cc = n0 + wn + nj * 8 + 2 * t;
                const float b0 = bias[cc], b1 = bias[cc + 1];
                float v0 = acc[mi][nj][0] + b0;
                float v1 = acc[mi][nj][1] + b1;
                float v2 = acc[mi][nj][2] + b0;
                float v3 = acc[mi][nj][3] + b1;
                if (SILU) {
                    v0 = silu_f(v0); v1 = silu_f(v1);
                    v2 = silu_f(v2); v3 = silu_f(v3);
                }
                if (OBF16) {
                    uint32_t lo0, lo1;
                    uint32_t hi0 = pack_hi2(v0, v1, &lo0);
                    uint32_t hi1 = pack_hi2(v2, v3, &lo1);
                    *(uint32_t*)&Ch[(size_t)r0 * N + cc]       = hi0;
                    *(uint32_t*)&Cl[(size_t)r0 * N + cc]       = lo0;
                    *(uint32_t*)&Ch[(size_t)(r0 + 8) * N + cc] = hi1;
                    *(uint32_t*)&Cl[(size_t)(r0 + 8) * N + cc] = lo1;
                } else {
                    *(float2*)&C[(size_t)r0 * N + cc]       = make_float2(v0, v1);
                    *(float2*)&C[(size_t)(r0 + 8) * N + cc] = make_float2(v2, v3);
                }
            }
        }
    }
}

// ============================================================================
// HMMA flash attention — optimal-makespan static schedule (272 CTAs, all = 32
// k-tiles): CTAs 0-31 {qt15}; 32-255 pairs (14-p, p); 256-271 two qt7 items.
// Inner loops identical to proven R13 version.
// ============================================================================
#define AQT 128
#define AKT 64
#define APW 36
#define NQT (Ss / AQT)
#define ATTN_GRID 272

#define QH_OFF 0
#define QL_OFF (128 * APW)
#define BUF_OFF (2 * 128 * APW)
#define TILE_KV (64 * APW)
#define BUF_W (4 * TILE_KV)
#define ASMEM_BYTES ((BUF_OFF + 2 * BUF_W) * 4)

__global__ __launch_bounds__(256, 2)
void attn_hmma(const float* __restrict__ pos_w, float* __restrict__ y,
               const __nv_bfloat16* __restrict__ hh, const __nv_bfloat16* __restrict__ hl) {
    extern __shared__ __align__(16) uint32_t aw[];
    const uint32_t smb = smem_u32(aw);

    const int tid  = threadIdx.x;
    const int wid  = tid >> 5;
    const int lane = tid & 31;
    const int g = lane >> 2, t = lane & 3;
    const int li = lane >> 3, lr = lane & 7;
    const int a_row = (li & 1) * 8 + lr;
    const int a_wrd = (li >> 1) * 4;
    const int b_row = (li >> 1) * 8 + lr;
    const int b_wrd = (li & 1) * 4;

    // ---- static schedule: blockIdx.x -> up to 2 (bh, qt) items ----
    const int bx = (int)blockIdx.x;
    int nit, ibh[2], iqt[2];
    if (bx < 32) {
        nit = 1; ibh[0] = bx; iqt[0] = 15; ibh[1] = 0; iqt[1] = 0;
    } else if (bx < 256) {
        const int p = (bx - 32) >> 5, j = (bx - 32) & 31;
        nit = 2;
        ibh[0] = j; iqt[0] = 14 - p;
        ibh[1] = j; iqt[1] = p;
    } else {
        const int c = bx - 256;
        nit = 2;
        ibh[0] = 2 * c;     iqt[0] = 7;
        ibh[1] = 2 * c + 1; iqt[1] = 7;
    }

    const __nv_bfloat16* hh_b;
    const __nv_bfloat16* hl_b;

    auto issue_q = [&](int q_cta) {
        #pragma unroll
        for (int it = 0; it < 8; it++) {
            int idx = it * 256 + tid;
            int part = idx >> 10;
            int r = (idx >> 3) & 127;
            int q8 = idx & 7;
            const __nv_bfloat16* src =
                (part ? hl_b : hh_b) + (size_t)(q_cta + r) * FOURD + 1024 + q8 * 8;
            cp16(smb + ((part ? QL_OFF : QH_OFF) + r * APW + q8 * 4) * 4, src);
        }
    };
    auto issue_kv = [&](int jt, int buf) {
        const int k0 = jt * AKT;
        const uint32_t base = BUF_OFF + buf * BUF_W;
        #pragma unroll
        for (int it = 0; it < 8; it++) {
            int idx = it * 256 + tid;
            int part = idx >> 9;
            int r = (idx >> 3) & 63;
            int q8 = idx & 7;
            const __nv_bfloat16* bg = (part & 1) ? hl_b : hh_b;
            const int quarter = (part >> 1) ? 3072 : 2048;
            const __nv_bfloat16* src = bg + (size_t)(k0 + r) * FOURD + quarter + q8 * 8;
            cp16(smb + (base + part * TILE_KV + r * APW + q8 * 4) * 4, src);
        }
        cp_commit();
    };

    #pragma unroll 1
    for (int sel = 0; sel < nit; sel++) {
        const int bh = ibh[sel];
        const int b = bh >> 4, head = bh & 15;
        const int qt = iqt[sel];
        const int q_cta = qt * AQT;
        const int jtmax = 2 * qt + 1;
        const int q_warp = q_cta + wid * 16;

        hh_b = hh + (size_t)b * Ss * FOURD + head * HDim;
        hl_b = hl + (size_t)b * Ss * FOURD + head * HDim;

        __syncthreads();
        issue_q(q_cta);
        issue_kv(0, 0);

        float O[8][4];
        #pragma unroll
        for (int nj = 0; nj < 8; nj++)
            #pragma unroll
            for (int e = 0; e < 4; e++) O[nj][e] = 0.f;

        for (int jt = 0; jt <= jtmax; jt++) {
            cp_wait<0>();
            __syncthreads();
            if (jt < jtmax) issue_kv(jt + 1, (jt + 1) & 1);

            const uint32_t bufb = smb + (BUF_OFF + (jt & 1) * BUF_W) * 4;
            const uint32_t khB = bufb;
            const uint32_t klB = bufb + TILE_KV * 4;
            const uint32_t vhB = bufb + 2 * TILE_KV * 4;
            const uint32_t vlB = bufb + 3 * TILE_KV * 4;

            if (jt * AKT <= q_warp + 15) {
                float S[8][4];
                #pragma unroll
                for (int nj = 0; nj < 8; nj++)
                    #pragma unroll
                    for (int e = 0; e < 4; e++) S[nj][e] = 0.f;

                #pragma unroll
                for (int ks = 0; ks < 4; ks++) {
                    uint32_t ah[4], al[4];
                    const uint32_t qoff = ((wid * 16 + a_row) * APW + ks * 8 + a_wrd) * 4;
                    ldm_x4(ah, smb + QH_OFF * 4 + qoff);
                    ldm_x4(al, smb + QL_OFF * 4 + qoff);
                    #pragma unroll
                    for (int nj2 = 0; nj2 < 4; nj2++) {
                        uint32_t bh4[4], bl4[4];
                        const uint32_t koff = ((nj2 * 16 + b_row) * APW + ks * 8 + b_wrd) * 4;
                        ldm_x4(bh4, khB + koff);
                        ldm_x4(bl4, klB + koff);
                        mma_bf16(S[2*nj2],   ah, bh4);
                        mma_bf16(S[2*nj2],   ah, bl4);
                        mma_bf16(S[2*nj2],   al, bh4);
                        mma_bf16(S[2*nj2+1], ah, bh4 + 2);
                        mma_bf16(S[2*nj2+1], ah, bl4 + 2);
                        mma_bf16(S[2*nj2+1], al, bh4 + 2);
                    }
                }

                const int qg0 = q_warp + g;
                #pragma unroll
                for (int ks2 = 0; ks2 < 4; ks2++) {
                    uint32_t ph[4], pl[4];
                    #pragma unroll
                    for (int half = 0; half < 2; half++) {
                        const float* sc = S[2*ks2 + half];
                        const int kc = jt * AKT + (2*ks2 + half) * 8 + 2*t;
                        float p00 = silu_f(sc[0] + pos_w[Mm - 1 + kc     - qg0]);
                        float p01 = silu_f(sc[1] + pos_w[Mm - 1 + kc + 1 - qg0]);
                        float p10 = silu_f(sc[2] + pos_w[Mm - 1 + kc     - (qg0+8)]);
                        float p11 = silu_f(sc[3] + pos_w[Mm - 1 + kc + 1 - (qg0+8)]);
                        if (kc     > qg0)   p00 = 0.f;
                        if (kc + 1 > qg0)   p01 = 0.f;
                        if (kc     > qg0+8) p10 = 0.f;
                        if (kc + 1 > qg0+8) p11 = 0.f;
                        ph[0 + half*2] = pack_hi2(p00, p01, &pl[0 + half*2]);
                        ph[1 + half*2] = pack_hi2(p10, p11, &pl[1 + half*2]);
                    }
                    #pragma unroll
                    for (int nj2 = 0; nj2 < 4; nj2++) {
                        uint32_t vh4[4], vl4[4];
                        const uint32_t voff =
                            ((ks2 * 16 + (li & 1) * 8 + lr) * APW + nj2 * 8 + (li >> 1) * 4) * 4;
                        ldm_x4t(vh4, vhB + voff);
                        ldm_x4t(vl4, vlB + voff);
                        mma_bf16(O[2*nj2],   ph, vh4);
                        mma_bf16(O[2*nj2],   ph, vl4);
                        mma_bf16(O[2*nj2],   pl, vh4);
                        mma_bf16(O[2*nj2+1], ph, vh4 + 2);
                        mma_bf16(O[2*nj2+1], ph, vl4 + 2);
                        mma_bf16(O[2*nj2+1], pl, vh4 + 2);
                    }
                }
            }
        }

        #pragma unroll
        for (int nj = 0; nj < 8; nj++) {
            const int d = nj * 8 + 2 * t;
            #pragma unroll
            for (int half = 0; half < 2; half++) {
                const int q = q_warp + g + half * 8;
                const uint32_t uhp = *(const uint32_t*)&hh_b[(size_t)q * FOURD + d];
                const uint32_t ulp = *(const uint32_t*)&hl_b[(size_t)q * FOURD + d];
                const __nv_bfloat162 uh2 = *(const __nv_bfloat162*)&uhp;
                const __nv_bfloat162 ul2 = *(const __nv_bfloat162*)&ulp;
                float2 r;
                r.x = O[nj][half*2 + 0] * (__bfloat162float(uh2.x) + __bfloat162float(ul2.x));
                r.y = O[nj][half*2 + 1] * (__bfloat162float(uh2.y) + __bfloat162float(ul2.y));
                *(float2*)&y[((size_t)b * Ss + q) * Dd + head * HDim + d] = r;
            }
        }
    }
}

// ---------------- LayerNorm: warp-per-row, shfl-only ---------------------------
__device__ __forceinline__ float warp_allsum(float v) {
    #pragma unroll
    for (int o = 16; o > 0; o >>= 1) v += __shfl_xor_sync(0xffffffffu, v, o);
    return v;
}

template<bool BF16OUT>
__global__ __launch_bounds__(256)
void ln_kernel(const float* __restrict__ in, const float* __restrict__ res,
               const float* __restrict__ g, const float* __restrict__ beta,
               float* __restrict__ out,
               __nv_bfloat16* __restrict__ outh, __nv_bfloat16* __restrict__ outl) {
    const int lane = threadIdx.x & 31;
    const size_t row = (size_t)blockIdx.x * 8 + (threadIdx.x >> 5);

    float4 v[8];
    float s = 0.f;
    #pragma unroll
    for (int k = 0; k < 8; k++) {
        const int c = (k * 32 + lane) * 4;
        v[k] = *(const float4*)&in[row * Dd + c];
        if (res) {
            float4 r = *(const float4*)&res[row * Dd + c];
            v[k].x += r.x; v[k].y += r.y; v[k].z += r.z; v[k].w += r.w;
        }
        s += v[k].x + v[k].y + v[k].z + v[k].w;
    }
    const float mu = warp_allsum(s) * (1.f / Dd);

    float sq = 0.f;
    #pragma unroll
    for (int k = 0; k < 8; k++) {
        v[k].x -= mu; v[k].y -= mu; v[k].z -= mu; v[k].w -= mu;
        sq += v[k].x*v[k].x + v[k].y*v[k].y + v[k].z*v[k].z + v[k].w*v[k].w;
    }
    const float inv = rsqrtf(warp_allsum(sq) * (1.f / Dd) + EPS);

    #pragma unroll
    for (int k = 0; k < 8; k++) {
        const int c = (k * 32 + lane) * 4;
        float4 gv = *(const float4*)&g[c];
        float4 bv = *(const float4*)&beta[c];
        float4 r;
        r.x = v[k].x * inv * gv.x + bv.x;
        r.y = v[k].y * inv * gv.y + bv.y;
        r.z = v[k].z * inv * gv.z + bv.z;
        r.w = v[k].w * inv * gv.w + bv.w;
        if (BF16OUT) {
            float4 rem;
            uint2 h = cvt_hi(r, &rem);
            *(uint2*)&outh[row * Dd + c] = h;
            *(uint2*)&outl[row * Dd + c] = cvt_lo(rem);
        } else {
            *(float4*)&out[row * Dd + c] = r;
        }
    }
}

// ---------------- launch ------------------------------------------------------
extern "C" void kernel_launch(void* const* d_in, const int* in_sizes, int n_in,
                              void* d_out, int out_size) {
    const float* x     = (const float*)d_in[0];
    const float* w1    = (const float*)d_in[2];
    const float* b1    = (const float*)d_in[3];
    const float* w2    = (const float*)d_in[4];
    const float* b2    = (const float*)d_in[5];
    const float* g1    = (const float*)d_in[6];
    const float* beta1 = (const float*)d_in[7];
    const float* g2    = (const float*)d_in[8];
    const float* beta2 = (const float*)d_in[9];
    const float* pos_w = (const float*)d_in[10];
    float* out = (float*)d_out;

    float *ybuf, *tbuf;
    __nv_bfloat16 *xh, *xl, *w1h, *w1l, *w2h, *w2l, *zh, *zl, *hhp, *hlp;
    cudaGetSymbolAddress((void**)&ybuf, g_y);
    cudaGetSymbolAddress((void**)&tbuf, g_t);
    cudaGetSymbolAddress((void**)&xh,  g_xh);  cudaGetSymbolAddress((void**)&xl,  g_xl);
    cudaGetSymbolAddress((void**)&w1h, g_w1h); cudaGetSymbolAddress((void**)&w1l, g_w1l);
    cudaGetSymbolAddress((void**)&w2h, g_w2h); cudaGetSymbolAddress((void**)&w2l, g_w2l);
    cudaGetSymbolAddress((void**)&zh,  g_zh);  cudaGetSymbolAddress((void**)&zl,  g_zl);
    cudaGetSymbolAddress((void**)&hhp, g_hh);  cudaGetSymbolAddress((void**)&hlp, g_hl);

    cudaFuncSetAttribute((const void*)hmma_gemm_cp<true,true>,
                         cudaFuncAttributeMaxDynamicSharedMemorySize, GSMEM_BYTES);
    cudaFuncSetAttribute((const void*)hmma_gemm_cp<false,false>,
                         cudaFuncAttributeMaxDynamicSharedMemorySize, GSMEM_BYTES);
    cudaFuncSetAttribute((const void*)attn_hmma,
                         cudaFuncAttributeMaxDynamicSharedMemorySize, ASMEM_BYTES);

    // 0) pre-convert x, w1, w2 to bf16 hi/lo (single launch)
    cvt3_kernel<<<1184, 256>>>(x, xh, xl, NTOK * Dd / 4,
                               w1, w1h, w1l, FOURD * Dd / 4,
                               w2, w2h, w2l, Dd * Dd / 4);

    // 1) h = silu(x @ w1^T + b1) -> bf16 hi/lo  (persistent: 296 CTAs)
    hmma_gemm_cp<true,true><<<GPERSIST, 256, GSMEM_BYTES>>>(
        xh, xl, w1h, w1l, b1, nullptr, hhp, hlp, FOURD, Dd,
        (NTOK/BM) * (FOURD/BN));

    // 2) fused HMMA attention + u gate -> g_y  (272 CTAs, optimal makespan)
    attn_hmma<<<ATTN_GRID, 256, ASMEM_BYTES>>>(pos_w, ybuf, hhp, hlp);

    // 3) LN1 -> z (bf16 hi/lo)  (warp-per-row)
    ln_kernel<true><<<NTOK/8, 256>>>(ybuf, nullptr, g1, beta1, nullptr, zh, zl);

    // 4) t = z @ w2^T + b2 (fp32 out; 256 tiles, one per CTA)
    hmma_gemm_cp<false,false><<<(NTOK/BM) * (Dd/BN), 256, GSMEM_BYTES>>>(
        zh, zl, w2h, w2l, b2, tbuf, nullptr, nullptr, Dd, Dd,
        (NTOK/BM) * (Dd/BN));

    // 5) out = LN(t + x)
    ln_kernel<false><<<NTOK/8, 256>>>(tbuf, x, g2, beta2, out, nullptr, nullptr);
}

// round 15
// speedup vs baseline: 1.0897x; 1.0295x over previous
#include <cuda_runtime.h>
#include <cuda_bf16.h>
#include <cstdint>
#include <cstddef>

// Problem constants
#define Bb 2
#define Ss 2048
#define Dd 1024
#define Hh 16
#define HDim 64
#define Mm 4096
#define NTOK (Bb*Ss)          // 4096
#define FOURD (4*Dd)          // 4096
#define EPS 1e-5f

// ---------------- scratch ----------------------------------------------------
__device__ float g_y[(size_t)NTOK * Dd];      // gated attention out
__device__ float g_t[(size_t)NTOK * Dd];      // GEMM2 out
__device__ __nv_bfloat16 g_xh[(size_t)NTOK * Dd],  g_xl[(size_t)NTOK * Dd];
__device__ __nv_bfloat16 g_w1h[(size_t)FOURD * Dd], g_w1l[(size_t)FOURD * Dd];
__device__ __nv_bfloat16 g_w2h[(size_t)Dd * Dd],   g_w2l[(size_t)Dd * Dd];
__device__ __nv_bfloat16 g_zh[(size_t)NTOK * Dd],  g_zl[(size_t)NTOK * Dd];
__device__ __nv_bfloat16 g_hh[(size_t)NTOK * FOURD], g_hl[(size_t)NTOK * FOURD];

// ---------------- common helpers ----------------------------------------------
__device__ __forceinline__ void mma_bf16(float* c, const uint32_t* a, const uint32_t* b) {
    asm volatile(
        "mma.sync.aligned.m16n8k16.row.col.f32.bf16.bf16.f32 "
        "{%0,%1,%2,%3}, {%4,%5,%6,%7}, {%8,%9}, {%0,%1,%2,%3};"
        : "+f"(c[0]), "+f"(c[1]), "+f"(c[2]), "+f"(c[3])
        : "r"(a[0]), "r"(a[1]), "r"(a[2]), "r"(a[3]), "r"(b[0]), "r"(b[1]));
}
__device__ __forceinline__ void ldm_x4(uint32_t* r, uint32_t addr) {
    asm volatile("ldmatrix.sync.aligned.m8n8.x4.shared.b16 {%0,%1,%2,%3}, [%4];"
        : "=r"(r[0]), "=r"(r[1]), "=r"(r[2]), "=r"(r[3]) : "r"(addr));
}
__device__ __forceinline__ void ldm_x4t(uint32_t* r, uint32_t addr) {
    asm volatile("ldmatrix.sync.aligned.m8n8.x4.trans.shared.b16 {%0,%1,%2,%3}, [%4];"
        : "=r"(r[0]), "=r"(r[1]), "=r"(r[2]), "=r"(r[3]) : "r"(addr));
}
__device__ __forceinline__ uint2 cvt_hi(float4 g, float4* rem) {
    __nv_bfloat16 h0 = __float2bfloat16(g.x), h1 = __float2bfloat16(g.y);
    __nv_bfloat16 h2 = __float2bfloat16(g.z), h3 = __float2bfloat16(g.w);
    rem->x = g.x - __bfloat162float(h0);
    rem->y = g.y - __bfloat162float(h1);
    rem->z = g.z - __bfloat162float(h2);
    rem->w = g.w - __bfloat162float(h3);
    __nv_bfloat162 p0(h0, h1), p1(h2, h3);
    return make_uint2(*(uint32_t*)&p0, *(uint32_t*)&p1);
}
__device__ __forceinline__ uint2 cvt_lo(float4 g) {
    __nv_bfloat16 l0 = __float2bfloat16(g.x), l1 = __float2bfloat16(g.y);
    __nv_bfloat16 l2 = __float2bfloat16(g.z), l3 = __float2bfloat16(g.w);
    __nv_bfloat162 p0(l0, l1), p1(l2, l3);
    return make_uint2(*(uint32_t*)&p0, *(uint32_t*)&p1);
}
__device__ __forceinline__ uint32_t pack_hi2(float a, float b, uint32_t* lo) {
    __nv_bfloat16 ha = __float2bfloat16(a), hb = __float2bfloat16(b);
    __nv_bfloat162 l(__float2bfloat16(a - __bfloat162float(ha)),
                     __float2bfloat16(b - __bfloat162float(hb)));
    *lo = *(uint32_t*)&l;
    __nv_bfloat162 h(ha, hb);
    return *(uint32_t*)&h;
}
__device__ __forceinline__ float silu_f(float v) {
    return v / (1.f + __expf(-v));
}
__device__ __forceinline__ uint32_t smem_u32(const void* p) {
    uint32_t a;
    asm("{ .reg .u64 t; cvta.to.shared.u64 t, %1; cvt.u32.u64 %0, t; }"
        : "=r"(a) : "l"(p));
    return a;
}
__device__ __forceinline__ void cp16(uint32_t dst, const void* src) {
    asm volatile("cp.async.cg.shared.global [%0], [%1], 16;" :: "r"(dst), "l"(src));
}
__device__ __forceinline__ void cp_commit() {
    asm volatile("cp.async.commit_group;" ::: "memory");
}
template<int N>
__device__ __forceinline__ void cp_wait() {
    asm volatile("cp.async.wait_group %0;" :: "n"(N) : "memory");
}

// ---------------- fp32 -> bf16 hi/lo converter (all 3 arrays, one launch) ------
__global__ __launch_bounds__(256)
void cvt3_kernel(const float* __restrict__ in0, __nv_bfloat16* __restrict__ h0,
                 __nv_bfloat16* __restrict__ l0, int n0,
                 const float* __restrict__ in1, __nv_bfloat16* __restrict__ h1,
                 __nv_bfloat16* __restrict__ l1, int n1,
                 const float* __restrict__ in2, __nv_bfloat16* __restrict__ h2,
                 __nv_bfloat16* __restrict__ l2, int n2) {
    const int total = n0 + n1 + n2;
    for (int i = blockIdx.x * 256 + threadIdx.x; i < total; i += gridDim.x * 256) {
        const float* in; __nv_bfloat16 *hi, *lo; int j;
        if (i < n0)            { in = in0; hi = h0; lo = l0; j = i; }
        else if (i < n0 + n1)  { in = in1; hi = h1; lo = l1; j = i - n0; }
        else                   { in = in2; hi = h2; lo = l2; j = i - n0 - n1; }
        float4 v = *(const float4*)&in[(size_t)j * 4];
        float4 rem;
        uint2 h = cvt_hi(v, &rem);
        *(uint2*)&hi[(size_t)j * 4] = h;
        *(uint2*)&lo[(size_t)j * 4] = cvt_lo(rem);
    }
}

// ============================================================================
// bf16 hi/lo HMMA GEMM — packed swizzled SMEM (no padding), 3-stage cp.async,
// 256 thr, 128x128 tile, 2 CTAs/SM, persistent.
// Layout: two 64B logical rows per 128B line; 16B unit u=(r&1)*4+q stored at
// u^((r>>1)&7). Conflict-free for ldmatrix phases and cp.async stores.
// ============================================================================
#define BM 128
#define BN 128
#define KC 32
#define TILE_B 8192                    // 128 rows x 64 B packed
#define STG_B  (4 * TILE_B)            // Ah, Al, Bh, Bl = 32768 B
#define GSMEM_BYTES (3 * STG_B)        // 98304
#define GPERSIST 296

__device__ __forceinline__ uint32_t swz_off(int r, int q) {
    return (uint32_t)(((r >> 1) << 7) + (((((r & 1) << 2) | q) ^ ((r >> 1) & 7)) << 4));
}

template<bool SILU, bool OBF16>
__global__ __launch_bounds__(256, 2)
void hmma_gemm_cp(const __nv_bfloat16* __restrict__ Ahg, const __nv_bfloat16* __restrict__ Alg,
                  const __nv_bfloat16* __restrict__ Bhg, const __nv_bfloat16* __restrict__ Blg,
                  const float* __restrict__ bias, float* __restrict__ C,
                  __nv_bfloat16* __restrict__ Ch, __nv_bfloat16* __restrict__ Cl,
                  int N, int K, int ntiles) {
    extern __shared__ __align__(1024) uint32_t sw[];
    const uint32_t smb = smem_u32(sw);
    const int tid  = threadIdx.x;
    const int lane = tid & 31;
    const int wid  = tid >> 5;
    const int g = lane >> 2, t = lane & 3;
    const int wm = (wid >> 2) * 64;
    const int wn = (wid & 3) * 32;
    const int ntN = N / BN;

    const int li = lane >> 3, lr = lane & 7;
    const int a_rbase = (li & 1) * 8 + lr;   // row within 16-row block
    const int a_qsel  = li >> 1;             // unit low bit
    const int b_rbase = (li >> 1) * 8 + lr;
    const int b_qsel  = li & 1;

    const __nv_bfloat16* tp[4] = {Ahg, Alg, Bhg, Blg};
    const int nc = K / KC;

    for (int tile = blockIdx.x; tile < ntiles; tile += gridDim.x) {
        const int m0 = (tile / ntN) * BM;
        const int n0 = (tile % ntN) * BN;

        __syncthreads();   // previous tile's reads complete

        auto issue_chunk = [&](int c) {
            const int k0 = c * KC;
            const uint32_t stg_b = smb + (uint32_t)(c % 3) * STG_B;
            #pragma unroll
            for (int it = 0; it < 8; it++) {
                int idx = it * 256 + tid;       // 0..2047 16B ops
                int tl = idx >> 9;              // 0..3
                int r = (idx >> 2) & 127;
                int q = idx & 3;
                int row = (tl < 2 ? m0 : n0) + r;
                const __nv_bfloat16* src = tp[tl] + (size_t)row * K + k0 + q * 8;
                cp16(stg_b + tl * TILE_B + swz_off(r, q), src);
            }
            cp_commit();
        };

        float acc[4][4][4];
        #pragma unroll
        for (int i = 0; i < 4; i++)
            #pragma unroll
            for (int j = 0; j < 4; j++)
                #pragma unroll
                for (int e = 0; e < 4; e++) acc[i][j][e] = 0.f;

        issue_chunk(0);
        if (nc > 1) issue_chunk(1);

        for (int c = 0; c < nc; c++) {
            if (c + 1 < nc) cp_wait<1>(); else cp_wait<0>();
            __syncthreads();

            const uint32_t stg = smb + (uint32_t)(c % 3) * STG_B;
            const uint32_t AhB = stg;
            const uint32_t AlB = stg +     TILE_B;
            const uint32_t BhB = stg + 2 * TILE_B;
            const uint32_t BlB = stg + 3 * TILE_B;

            // ---- ks = 0: fragments first, then issue chunk c+2 ----
            uint32_t ah[4][4], al[4][4], bh[2][4], bl[2][4];
            #pragma unroll
            for (int mi = 0; mi < 4; mi++) {
                const uint32_t ao = swz_off(wm + mi * 16 + a_rbase, a_qsel);
                ldm_x4(ah[mi], AhB + ao);
                ldm_x4(al[mi], AlB + ao);
            }
            #pragma unroll
            for (int njp = 0; njp < 2; njp++) {
                const uint32_t bo = swz_off(wn + njp * 16 + b_rbase, b_qsel);
                ldm_x4(bh[njp], BhB + bo);
                ldm_x4(bl[njp], BlB + bo);
            }
            if (c + 2 < nc) issue_chunk(c + 2);
            #pragma unroll
            for (int mi = 0; mi < 4; mi++)
                #pragma unroll
                for (int nj = 0; nj < 4; nj++) {
                    const uint32_t* bhp = &bh[nj >> 1][(nj & 1) * 2];
                    const uint32_t* blp = &bl[nj >> 1][(nj & 1) * 2];
                    mma_bf16(acc[mi][nj], ah[mi], bhp);
                    mma_bf16(acc[mi][nj], ah[mi], blp);
                    mma_bf16(acc[mi][nj], al[mi], bhp);
                }

            // ---- ks = 1 (units 2,3) ----
            #pragma unroll
            for (int mi = 0; mi < 4; mi++) {
                const uint32_t ao = swz_off(wm + mi * 16 + a_rbase, 2 + a_qsel);
                ldm_x4(ah[mi], AhB + ao);
                ldm_x4(al[mi], AlB + ao);
            }
            #pragma unroll
            for (int njp = 0; njp < 2; njp++) {
                const uint32_t bo = swz_off(wn + njp * 16 + b_rbase, 2 + b_qsel);
                ldm_x4(bh[njp], BhB + bo);
                ldm_x4(bl[njp], BlB + bo);
            }
            #pragma unroll
            for (int mi = 0; mi < 4; mi++)
                #pragma unroll
                for (int nj = 0; nj < 4; nj++) {
                    const uint32_t* bhp = &bh[nj >> 1][(nj & 1) * 2];
                    const uint32_t* blp = &bl[nj >> 1][(nj & 1) * 2];
                    mma_bf16(acc[mi][nj], ah[mi], bhp);
                    mma_bf16(acc[mi][nj], ah[mi], blp);
                    mma_bf16(acc[mi][nj], al[mi], bhp);
                }
        }

        // ---- epilogue ----
        #pragma unroll
        for (int mi = 0; mi < 4; mi++) {
            const int r0 = m0 + wm + mi * 16 + g;
            #pragma unroll
            for (int nj = 0; nj < 4; nj++) {
                const int cc = n0 + wn + nj * 8 + 2 * t;
                const float b0 = bias[cc], b1 = bias[cc + 1];
                float v0 = acc[mi][nj][0] + b0;
                float v1 = acc[mi][nj][1] + b1;
                float v2 = acc[mi][nj][2] + b0;
                float v3 = acc[mi][nj][3] + b1;
                if (SILU) {
                    v0 = silu_f(v0); v1 = silu_f(v1);
                    v2 = silu_f(v2); v3 = silu_f(v3);
                }
                if (OBF16) {
                    uint32_t lo0, lo1;
                    uint32_t hi0 = pack_hi2(v0, v1, &lo0);
                    uint32_t hi1 = pack_hi2(v2, v3, &lo1);
                    *(uint32_t*)&Ch[(size_t)r0 * N + cc]       = hi0;
                    *(uint32_t*)&Cl[(size_t)r0 * N + cc]       = lo0;
                    *(uint32_t*)&Ch[(size_t)(r0 + 8) * N + cc] = hi1;
                    *(uint32_t*)&Cl[(size_t)(r0 + 8) * N + cc] = lo1;
                } else {
                    *(float2*)&C[(size_t)r0 * N + cc]       = make_float2(v0, v1);
                    *(float2*)&C[(size_t)(r0 + 8) * N + cc] = make_float2(v2, v3);
                }
            }
        }
    }
}

// ============================================================================
// HMMA flash attention — optimal-makespan static schedule (R14, proven)
// ============================================================================
#define AQT 128
#define AKT 64
#define APW 36
#define NQT (Ss / AQT)
#define ATTN_GRID 272

#define QH_OFF 0
#define QL_OFF (128 * APW)
#define BUF_OFF (2 * 128 * APW)
#define TILE_KV (64 * APW)
#define BUF_W (4 * TILE_KV)
#define ASMEM_BYTES ((BUF_OFF + 2 * BUF_W) * 4)

__global__ __launch_bounds__(256, 2)
void attn_hmma(const float* __restrict__ pos_w, float* __restrict__ y,
               const __nv_bfloat16* __restrict__ hh, const __nv_bfloat16* __restrict__ hl) {
    extern __shared__ __align__(16) uint32_t aw[];
    const uint32_t smb = smem_u32(aw);

    const int tid  = threadIdx.x;
    const int wid  = tid >> 5;
    const int lane = tid & 31;
    const int g = lane >> 2, t = lane & 3;
    const int li = lane >> 3, lr = lane & 7;
    const int a_row = (li & 1) * 8 + lr;
    const int a_wrd = (li >> 1) * 4;
    const int b_row = (li >> 1) * 8 + lr;
    const int b_wrd = (li & 1) * 4;

    const int bx = (int)blockIdx.x;
    int nit, ibh[2], iqt[2];
    if (bx < 32) {
        nit = 1; ibh[0] = bx; iqt[0] = 15; ibh[1] = 0; iqt[1] = 0;
    } else if (bx < 256) {
        const int p = (bx - 32) >> 5, j = (bx - 32) & 31;
        nit = 2;
        ibh[0] = j; iqt[0] = 14 - p;
        ibh[1] = j; iqt[1] = p;
    } else {
        const int c = bx - 256;
        nit = 2;
        ibh[0] = 2 * c;     iqt[0] = 7;
        ibh[1] = 2 * c + 1; iqt[1] = 7;
    }

    const __nv_bfloat16* hh_b;
    const __nv_bfloat16* hl_b;

    auto issue_q = [&](int q_cta) {
        #pragma unroll
        for (int it = 0; it < 8; it++) {
            int idx = it * 256 + tid;
            int part = idx >> 10;
            int r = (idx >> 3) & 127;
            int q8 = idx & 7;
            const __nv_bfloat16* src =
                (part ? hl_b : hh_b) + (size_t)(q_cta + r) * FOURD + 1024 + q8 * 8;
            cp16(smb + ((part ? QL_OFF : QH_OFF) + r * APW + q8 * 4) * 4, src);
        }
    };
    auto issue_kv = [&](int jt, int buf) {
        const int k0 = jt * AKT;
        const uint32_t base = BUF_OFF + buf * BUF_W;
        #pragma unroll
        for (int it = 0; it < 8; it++) {
            int idx = it * 256 + tid;
            int part = idx >> 9;
            int r = (idx >> 3) & 63;
            int q8 = idx & 7;
            const __nv_bfloat16* bg = (part & 1) ? hl_b : hh_b;
            const int quarter = (part >> 1) ? 3072 : 2048;
            const __nv_bfloat16* src = bg + (size_t)(k0 + r) * FOURD + quarter + q8 * 8;
            cp16(smb + (base + part * TILE_KV + r * APW + q8 * 4) * 4, src);
        }
        cp_commit();
    };

    #pragma unroll 1
    for (int sel = 0; sel < nit; sel++) {
        const int bh = ibh[sel];
        const int b = bh >> 4, head = bh & 15;
        const int qt = iqt[sel];
        const int q_cta = qt * AQT;
        const int jtmax = 2 * qt + 1;
        const int q_warp = q_cta + wid * 16;

        hh_b = hh + (size_t)b * Ss * FOURD + head * HDim;
        hl_b = hl + (size_t)b * Ss * FOURD + head * HDim;

        __syncthreads();
        issue_q(q_cta);
        issue_kv(0, 0);

        float O[8][4];
        #pragma unroll
        for (int nj = 0; nj < 8; nj++)
            #pragma unroll
            for (int e = 0; e < 4; e++) O[nj][e] = 0.f;

        for (int jt = 0; jt <= jtmax; jt++) {
            cp_wait<0>();
            __syncthreads();
            if (jt < jtmax) issue_kv(jt + 1, (jt + 1) & 1);

            const uint32_t bufb = smb + (BUF_OFF + (jt & 1) * BUF_W) * 4;
            const uint32_t khB = bufb;
            const uint32_t klB = bufb + TILE_KV * 4;
            const uint32_t vhB = bufb + 2 * TILE_KV * 4;
            const uint32_t vlB = bufb + 3 * TILE_KV * 4;

            if (jt * AKT <= q_warp + 15) {
                float S[8][4];
                #pragma unroll
                for (int nj = 0; nj < 8; nj++)
                    #pragma unroll
                    for (int e = 0; e < 4; e++) S[nj][e] = 0.f;

                #pragma unroll
                for (int ks = 0; ks < 4; ks++) {
                    uint32_t ah[4], al[4];
                    const uint32_t qoff = ((wid * 16 + a_row) * APW + ks * 8 + a_wrd) * 4;
                    ldm_x4(ah, smb + QH_OFF * 4 + qoff);
                    ldm_x4(al, smb + QL_OFF * 4 + qoff);
                    #pragma unroll
                    for (int nj2 = 0; nj2 < 4; nj2++) {
                        uint32_t bh4[4], bl4[4];
                        const uint32_t koff = ((nj2 * 16 + b_row) * APW + ks * 8 + b_wrd) * 4;
                        ldm_x4(bh4, khB + koff);
                        ldm_x4(bl4, klB + koff);
                        mma_bf16(S[2*nj2],   ah, bh4);
                        mma_bf16(S[2*nj2],   ah, bl4);
                        mma_bf16(S[2*nj2],   al, bh4);
                        mma_bf16(S[2*nj2+1], ah, bh4 + 2);
                        mma_bf16(S[2*nj2+1], ah, bl4 + 2);
                        mma_bf16(S[2*nj2+1], al, bh4 + 2);
                    }
                }

                const int qg0 = q_warp + g;
                #pragma unroll
                for (int ks2 = 0; ks2 < 4; ks2++) {
                    uint32_t ph[4], pl[4];
                    #pragma unroll
                    for (int half = 0; half < 2; half++) {
                        const float* sc = S[2*ks2 + half];
                        const int kc = jt * AKT + (2*ks2 + half) * 8 + 2*t;
                        float p00 = silu_f(sc[0] + pos_w[Mm - 1 + kc     - qg0]);
                        float p01 = silu_f(sc[1] + pos_w[Mm - 1 + kc + 1 - qg0]);
                        float p10 = silu_f(sc[2] + pos_w[Mm - 1 + kc     - (qg0+8)]);
                        float p11 = silu_f(sc[3] + pos_w[Mm - 1 + kc + 1 - (qg0+8)]);
                        if (kc     > qg0)   p00 = 0.f;
                        if (kc + 1 > qg0)   p01 = 0.f;
                        if (kc     > qg0+8) p10 = 0.f;
                        if (kc + 1 > qg0+8) p11 = 0.f;
                        ph[0 + half*2] = pack_hi2(p00, p01, &pl[0 + half*2]);
                        ph[1 + half*2] = pack_hi2(p10, p11, &pl[1 + half*2]);
                    }
                    #pragma unroll
                    for (int nj2 = 0; nj2 < 4; nj2++) {
                        uint32_t vh4[4], vl4[4];
                        const uint32_t voff =
                            ((ks2 * 16 + (li & 1) * 8 + lr) * APW + nj2 * 8 + (li >> 1) * 4) * 4;
                        ldm_x4t(vh4, vhB + voff);
                        ldm_x4t(vl4, vlB + voff);
                        mma_bf16(O[2*nj2],   ph, vh4);
                        mma_bf16(O[2*nj2],   ph, vl4);
                        mma_bf16(O[2*nj2],   pl, vh4);
                        mma_bf16(O[2*nj2+1], ph, vh4 + 2);
                        mma_bf16(O[2*nj2+1], ph, vl4 + 2);
                        mma_bf16(O[2*nj2+1], pl, vh4 + 2);
                    }
                }
            }
        }

        #pragma unroll
        for (int nj = 0; nj < 8; nj++) {
            const int d = nj * 8 + 2 * t;
            #pragma unroll
            for (int half = 0; half < 2; half++) {
                const int q = q_warp + g + half * 8;
                const uint32_t uhp = *(const uint32_t*)&hh_b[(size_t)q * FOURD + d];
                const uint32_t ulp = *(const uint32_t*)&hl_b[(size_t)q * FOURD + d];
                const __nv_bfloat162 uh2 = *(const __nv_bfloat162*)&uhp;
                const __nv_bfloat162 ul2 = *(const __nv_bfloat162*)&ulp;
                float2 r;
                r.x = O[nj][half*2 + 0] * (__bfloat162float(uh2.x) + __bfloat162float(ul2.x));
                r.y = O[nj][half*2 + 1] * (__bfloat162float(uh2.y) + __bfloat162float(ul2.y));
                *(float2*)&y[((size_t)b * Ss + q) * Dd + head * HDim + d] = r;
            }
        }
    }
}

// ---------------- LayerNorm: warp-per-row, shfl-only ---------------------------
__device__ __forceinline__ float warp_allsum(float v) {
    #pragma unroll
    for (int o = 16; o > 0; o >>= 1) v += __shfl_xor_sync(0xffffffffu, v, o);
    return v;
}

template<bool BF16OUT>
__global__ __launch_bounds__(256)
void ln_kernel(const float* __restrict__ in, const float* __restrict__ res,
               const float* __restrict__ g, const float* __restrict__ beta,
               float* __restrict__ out,
               __nv_bfloat16* __restrict__ outh, __nv_bfloat16* __restrict__ outl) {
    const int lane = threadIdx.x & 31;
    const size_t row = (size_t)blockIdx.x * 8 + (threadIdx.x >> 5);

    float4 v[8];
    float s = 0.f;
    #pragma unroll
    for (int k = 0; k < 8; k++) {
        const int c = (k * 32 + lane) * 4;
        v[k] = *(const float4*)&in[row * Dd + c];
        if (res) {
            float4 r = *(const float4*)&res[row * Dd + c];
            v[k].x += r.x; v[k].y += r.y; v[k].z += r.z; v[k].w += r.w;
        }
        s += v[k].x + v[k].y + v[k].z + v[k].w;
    }
    const float mu = warp_allsum(s) * (1.f / Dd);

    float sq = 0.f;
    #pragma unroll
    for (int k = 0; k < 8; k++) {
        v[k].x -= mu; v[k].y -= mu; v[k].z -= mu; v[k].w -= mu;
        sq += v[k].x*v[k].x + v[k].y*v[k].y + v[k].z*v[k].z + v[k].w*v[k].w;
    }
    const float inv = rsqrtf(warp_allsum(sq) * (1.f / Dd) + EPS);

    #pragma unroll
    for (int k = 0; k < 8; k++) {
        const int c = (k * 32 + lane) * 4;
        float4 gv = *(const float4*)&g[c];
        float4 bv = *(const float4*)&beta[c];
        float4 r;
        r.x = v[k].x * inv * gv.x + bv.x;
        r.y = v[k].y * inv * gv.y + bv.y;
        r.z = v[k].z * inv * gv.z + bv.z;
        r.w = v[k].w * inv * gv.w + bv.w;
        if (BF16OUT) {
            float4 rem;
            uint2 h = cvt_hi(r, &rem);
            *(uint2*)&outh[row * Dd + c] = h;
            *(uint2*)&outl[row * Dd + c] = cvt_lo(rem);
        } else {
            *(float4*)&out[row * Dd + c] = r;
        }
    }
}

// ---------------- launch ------------------------------------------------------
extern "C" void kernel_launch(void* const* d_in, const int* in_sizes, int n_in,
                              void* d_out, int out_size) {
    const float* x     = (const float*)d_in[0];
    const float* w1    = (const float*)d_in[2];
    const float* b1    = (const float*)d_in[3];
    const float* w2    = (const float*)d_in[4];
    const float* b2    = (const float*)d_in[5];
    const float* g1    = (const float*)d_in[6];
    const float* beta1 = (const float*)d_in[7];
    const float* g2    = (const float*)d_in[8];
    const float* beta2 = (const float*)d_in[9];
    const float* pos_w = (const float*)d_in[10];
    float* out = (float*)d_out;

    float *ybuf, *tbuf;
    __nv_bfloat16 *xh, *xl, *w1h, *w1l, *w2h, *w2l, *zh, *zl, *hhp, *hlp;
    cudaGetSymbolAddress((void**)&ybuf, g_y);
    cudaGetSymbolAddress((void**)&tbuf, g_t);
    cudaGetSymbolAddress((void**)&xh,  g_xh);  cudaGetSymbolAddress((void**)&xl,  g_xl);
    cudaGetSymbolAddress((void**)&w1h, g_w1h); cudaGetSymbolAddress((void**)&w1l, g_w1l);
    cudaGetSymbolAddress((void**)&w2h, g_w2h); cudaGetSymbolAddress((void**)&w2l, g_w2l);
    cudaGetSymbolAddress((void**)&zh,  g_zh);  cudaGetSymbolAddress((void**)&zl,  g_zl);
    cudaGetSymbolAddress((void**)&hhp, g_hh);  cudaGetSymbolAddress((void**)&hlp, g_hl);

    cudaFuncSetAttribute((const void*)hmma_gemm_cp<true,true>,
                         cudaFuncAttributeMaxDynamicSharedMemorySize, GSMEM_BYTES);
    cudaFuncSetAttribute((const void*)hmma_gemm_cp<false,false>,
                         cudaFuncAttributeMaxDynamicSharedMemorySize, GSMEM_BYTES);
    cudaFuncSetAttribute((const void*)attn_hmma,
                         cudaFuncAttributeMaxDynamicSharedMemorySize, ASMEM_BYTES);

    // 0) pre-convert x, w1, w2 to bf16 hi/lo (single launch)
    cvt3_kernel<<<1184, 256>>>(x, xh, xl, NTOK * Dd / 4,
                               w1, w1h, w1l, FOURD * Dd / 4,
                               w2, w2h, w2l, Dd * Dd / 4);

    // 1) h = silu(x @ w1^T + b1) -> bf16 hi/lo  (persistent: 296 CTAs)
    hmma_gemm_cp<true,true><<<GPERSIST, 256, GSMEM_BYTES>>>(
        xh, xl, w1h, w1l, b1, nullptr, hhp, hlp, FOURD, Dd,
        (NTOK/BM) * (FOURD/BN));

    // 2) fused HMMA attention + u gate -> g_y  (272 CTAs, optimal makespan)
    attn_hmma<<<ATTN_GRID, 256, ASMEM_BYTES>>>(pos_w, ybuf, hhp, hlp);

    // 3) LN1 -> z (bf16 hi/lo)  (warp-per-row)
    ln_kernel<true><<<NTOK/8, 256>>>(ybuf, nullptr, g1, beta1, nullptr, zh, zl);

    // 4) t = z @ w2^T + b2 (fp32 out; 256 tiles, one per CTA)
    hmma_gemm_cp<false,false><<<(NTOK/BM) * (Dd/BN), 256, GSMEM_BYTES>>>(
        zh, zl, w2h, w2l, b2, tbuf, nullptr, nullptr, Dd, Dd,
        (NTOK/BM) * (Dd/BN));

    // 5) out = LN(t + x)
    ln_kernel<false><<<NTOK/8, 256>>>(tbuf, x, g2, beta2, out, nullptr, nullptr);
}